// round 1
// baseline (speedup 1.0000x reference)
#include <cuda_runtime.h>
#include <math_constants.h>

// Problem constants
#define BB    32
#define SS    512
#define MM    8
#define HH    512           // DIM2 / hidden
#define DIM1_ 2048
#define WCOLS 2560          // DIM1 + DIM2
#define EPSF  1e-5f

// Scratch (device globals — no allocation allowed)
__device__ float g_pb[(size_t)BB * SS * HH];   // part_base [B*S, H]  (33.5 MB)
__device__ float g_pm[BB * MM * HH];           // part_mem + b1
__device__ float g_e [BB * MM * SS];           // logits e[b, m*S+s]

// ---------------------------------------------------------------------------
// Kernel 1: part_base = base @ W1a^T.   base is the virtual concat
// [face | fc | img | label(bcast over s)] of width 2048; rows r = b*S+s.
// Classic 128x128x16 double-buffered SGEMM, 8x8 register microtile.
// ---------------------------------------------------------------------------
#define BM 128
#define BN 128
#define BK 16
#define PADLD 132

__device__ __forceinline__ const float* base_ptr(
    const float* __restrict__ face, const float* __restrict__ fc,
    const float* __restrict__ img,  const float* __restrict__ label,
    int r, int d)
{
    const int f   = d >> 9;       // which feature (k-tile uniform: BK=16 divides 512)
    const int off = d & 511;
    if (f == 0) return face  + (size_t)r * 512 + off;
    if (f == 1) return fc    + (size_t)r * 512 + off;
    if (f == 2) return img   + (size_t)r * 512 + off;
    return label + (size_t)(r >> 9) * 512 + off;   // b = r / S, S == 512
}

__global__ __launch_bounds__(256, 2)
void gemm_pb_kernel(const float* __restrict__ face, const float* __restrict__ fc,
                    const float* __restrict__ img,  const float* __restrict__ label,
                    const float* __restrict__ W1)
{
    __shared__ float As[2][BK][PADLD];
    __shared__ float Bs[2][BK][PADLD];

    const int tid     = threadIdx.x;
    const int rowBase = blockIdx.y * BM;
    const int colBase = blockIdx.x * BN;
    const int tx = tid & 15;          // 16 columns of threads
    const int ty = tid >> 4;          // 16 rows of threads

    const int r0 = tid >> 2;          // 0..63 (two passes cover 128 tile rows)
    const int kv = (tid & 3) * 4;     // float4 slot within the 16-wide k tile

    float acc[8][8];
#pragma unroll
    for (int i = 0; i < 8; i++)
#pragma unroll
        for (int j = 0; j < 8; j++) acc[i][j] = 0.f;

    // Preload tile 0 into buffer 0
#pragma unroll
    for (int t = 0; t < 2; t++) {
        const int row = r0 + t * 64;
        const float4 va = *(const float4*)base_ptr(face, fc, img, label, rowBase + row, kv);
        As[0][kv + 0][row] = va.x; As[0][kv + 1][row] = va.y;
        As[0][kv + 2][row] = va.z; As[0][kv + 3][row] = va.w;
        const float4 vb = *(const float4*)&W1[(size_t)(colBase + row) * WCOLS + kv];
        Bs[0][kv + 0][row] = vb.x; Bs[0][kv + 1][row] = vb.y;
        Bs[0][kv + 2][row] = vb.z; Bs[0][kv + 3][row] = vb.w;
    }
    __syncthreads();

    const int NK = DIM1_ / BK;   // 128 k-tiles
    float4 na[2], nb[2];

    for (int kt = 0; kt < NK; kt++) {
        const int cur = kt & 1;

        if (kt + 1 < NK) {
            const int d0 = (kt + 1) * BK;
#pragma unroll
            for (int t = 0; t < 2; t++) {
                const int row = r0 + t * 64;
                na[t] = *(const float4*)base_ptr(face, fc, img, label, rowBase + row, d0 + kv);
                nb[t] = *(const float4*)&W1[(size_t)(colBase + row) * WCOLS + d0 + kv];
            }
        }

#pragma unroll
        for (int kk = 0; kk < BK; kk++) {
            float a[8], b[8];
            *(float4*)&a[0] = *(const float4*)&As[cur][kk][ty * 8];
            *(float4*)&a[4] = *(const float4*)&As[cur][kk][ty * 8 + 4];
            *(float4*)&b[0] = *(const float4*)&Bs[cur][kk][tx * 8];
            *(float4*)&b[4] = *(const float4*)&Bs[cur][kk][tx * 8 + 4];
#pragma unroll
            for (int i = 0; i < 8; i++)
#pragma unroll
                for (int j = 0; j < 8; j++)
                    acc[i][j] = fmaf(a[i], b[j], acc[i][j]);
        }

        if (kt + 1 < NK) {
            const int nxt = cur ^ 1;
#pragma unroll
            for (int t = 0; t < 2; t++) {
                const int row = r0 + t * 64;
                As[nxt][kv + 0][row] = na[t].x; As[nxt][kv + 1][row] = na[t].y;
                As[nxt][kv + 2][row] = na[t].z; As[nxt][kv + 3][row] = na[t].w;
                Bs[nxt][kv + 0][row] = nb[t].x; Bs[nxt][kv + 1][row] = nb[t].y;
                Bs[nxt][kv + 2][row] = nb[t].z; Bs[nxt][kv + 3][row] = nb[t].w;
            }
        }
        __syncthreads();
    }

    // Epilogue: write pb
#pragma unroll
    for (int i = 0; i < 8; i++) {
        const size_t base = (size_t)(rowBase + ty * 8 + i) * HH + colBase + tx * 8;
        *(float4*)&g_pb[base]     = make_float4(acc[i][0], acc[i][1], acc[i][2], acc[i][3]);
        *(float4*)&g_pb[base + 4] = make_float4(acc[i][4], acc[i][5], acc[i][6], acc[i][7]);
    }
}

// ---------------------------------------------------------------------------
// Kernel 2: part_mem[b,m,h] = memory[b,m,:] . W1[h, 2048:2560] + b1[h]
// One warp per output; tiny workload, L2-resident.
// ---------------------------------------------------------------------------
__global__ __launch_bounds__(256)
void pm_kernel(const float* __restrict__ memory, const float* __restrict__ W1,
               const float* __restrict__ b1)
{
    const int gw   = (blockIdx.x * blockDim.x + threadIdx.x) >> 5;  // 0 .. B*M*H-1
    const int lane = threadIdx.x & 31;
    const int h  = gw & (HH - 1);
    const int bm = gw >> 9;

    const float* __restrict__ wrow = W1 + (size_t)h * WCOLS + DIM1_;
    const float* __restrict__ mrow = memory + (size_t)bm * HH;

    float acc = 0.f;
#pragma unroll 4
    for (int d = lane; d < HH; d += 32) acc = fmaf(wrow[d], mrow[d], acc);
#pragma unroll
    for (int o = 16; o; o >>= 1) acc += __shfl_xor_sync(0xFFFFFFFFu, acc, o);
    if (lane == 0) g_pm[gw] = acc + b1[h];
}

// ---------------------------------------------------------------------------
// Kernel 3: e[b, m*S+s] = sum_h w2[h] * tanh(pb[b,s,h] + pm[b,m,h])
// Warp per s; each pb element loaded once, 8 tanh (one per m) per element.
// ---------------------------------------------------------------------------
__global__ __launch_bounds__(256)
void e_kernel(const float* __restrict__ w2)
{
    __shared__ float pm_s[MM][HH];
    __shared__ float w2_s[HH];

    const int b   = blockIdx.y;
    const int tid = threadIdx.x;
    for (int i = tid; i < MM * HH; i += 256) ((float*)pm_s)[i] = g_pm[b * MM * HH + i];
    for (int i = tid; i < HH; i += 256)      w2_s[i] = w2[i];
    __syncthreads();

    const int warp = tid >> 5, lane = tid & 31;
    const int s = blockIdx.x * 8 + warp;
    const float* __restrict__ pb = g_pb + (size_t)(b * SS + s) * HH;

    float acc[MM];
#pragma unroll
    for (int m = 0; m < MM; m++) acc[m] = 0.f;

    for (int h = lane; h < HH; h += 32) {
        const float pbv = pb[h];
        const float w2v = w2_s[h];
#pragma unroll
        for (int m = 0; m < MM; m++)
            acc[m] = fmaf(w2v, tanhf(pbv + pm_s[m][h]), acc[m]);
    }
#pragma unroll
    for (int m = 0; m < MM; m++)
#pragma unroll
        for (int o = 16; o; o >>= 1) acc[m] += __shfl_xor_sync(0xFFFFFFFFu, acc[m], o);

    if (lane == 0) {
#pragma unroll
        for (int m = 0; m < MM; m++) g_e[b * MM * SS + m * SS + s] = acc[m];
    }
}

// ---------------------------------------------------------------------------
// Kernel 4: softmax over 4096, then *mask, then renorm by (masked_sum + EPS).
// One block (1024 threads) per batch; 4 elements/thread held in registers.
// ---------------------------------------------------------------------------
__global__ __launch_bounds__(1024)
void softmax_kernel(const float* __restrict__ face_mask, float* __restrict__ alpha)
{
    __shared__ float sred[32];
    const int b = blockIdx.x;
    const int tid = threadIdx.x;
    const int w = tid >> 5, l = tid & 31;
    const float* __restrict__ e = g_e + b * (MM * SS);

    float v[4];
    float mx = -CUDART_INF_F;
#pragma unroll
    for (int i = 0; i < 4; i++) { v[i] = e[tid + i * 1024]; mx = fmaxf(mx, v[i]); }

    // block max
#pragma unroll
    for (int o = 16; o; o >>= 1) mx = fmaxf(mx, __shfl_xor_sync(0xFFFFFFFFu, mx, o));
    if (l == 0) sred[w] = mx;
    __syncthreads();
    if (tid < 32) {
        float t = sred[tid];
#pragma unroll
        for (int o = 16; o; o >>= 1) t = fmaxf(t, __shfl_xor_sync(0xFFFFFFFFu, t, o));
        if (tid == 0) sred[0] = t;
    }
    __syncthreads();
    mx = sred[0];
    __syncthreads();

    // exp + block sum (full softmax denominator, includes masked entries)
    float sum = 0.f;
#pragma unroll
    for (int i = 0; i < 4; i++) { v[i] = __expf(v[i] - mx); sum += v[i]; }
#pragma unroll
    for (int o = 16; o; o >>= 1) sum += __shfl_xor_sync(0xFFFFFFFFu, sum, o);
    if (l == 0) sred[w] = sum;
    __syncthreads();
    if (tid < 32) {
        float t = sred[tid];
#pragma unroll
        for (int o = 16; o; o >>= 1) t += __shfl_xor_sync(0xFFFFFFFFu, t, o);
        if (tid == 0) sred[0] = t;
    }
    __syncthreads();
    const float Z = sred[0];
    __syncthreads();

    // mask then masked-sum
    const float invZ = 1.f / Z;
    float msum = 0.f;
#pragma unroll
    for (int i = 0; i < 4; i++) {
        const int idx = tid + i * 1024;
        const float mk = face_mask[b * SS + (idx & 511)];
        v[i] = v[i] * invZ * mk;
        msum += v[i];
    }
#pragma unroll
    for (int o = 16; o; o >>= 1) msum += __shfl_xor_sync(0xFFFFFFFFu, msum, o);
    if (l == 0) sred[w] = msum;
    __syncthreads();
    if (tid < 32) {
        float t = sred[tid];
#pragma unroll
        for (int o = 16; o; o >>= 1) t += __shfl_xor_sync(0xFFFFFFFFu, t, o);
        if (tid == 0) sred[0] = t;
    }
    __syncthreads();
    const float inv = 1.f / (sred[0] + EPSF);

#pragma unroll
    for (int i = 0; i < 4; i++)
        alpha[b * (MM * SS) + tid + i * 1024] = v[i] * inv;
}

// ---------------------------------------------------------------------------
// Kernel 5: context[b,d] = sum_s (sum_m alpha[b,m,s]) * face[b,s,d]
// ---------------------------------------------------------------------------
__global__ __launch_bounds__(512)
void context_kernel(const float* __restrict__ face, const float* __restrict__ alpha,
                    float* __restrict__ ctx)
{
    __shared__ float asum[SS];
    const int b = blockIdx.x;
    const int tid = threadIdx.x;

    float a = 0.f;
#pragma unroll
    for (int m = 0; m < MM; m++) a += alpha[b * (MM * SS) + m * SS + tid];
    asum[tid] = a;
    __syncthreads();

    const float* __restrict__ fb = face + (size_t)b * SS * 512;
    float c0 = 0.f, c1 = 0.f, c2 = 0.f, c3 = 0.f;
    for (int s = 0; s < SS; s += 4) {
        c0 = fmaf(asum[s + 0], fb[(size_t)(s + 0) * 512 + tid], c0);
        c1 = fmaf(asum[s + 1], fb[(size_t)(s + 1) * 512 + tid], c1);
        c2 = fmaf(asum[s + 2], fb[(size_t)(s + 2) * 512 + tid], c2);
        c3 = fmaf(asum[s + 3], fb[(size_t)(s + 3) * 512 + tid], c3);
    }
    ctx[b * 512 + tid] = (c0 + c1) + (c2 + c3);
}

// ---------------------------------------------------------------------------
// Launch. Inputs in setup_inputs() order:
// 0 fc_feat, 1 img_feat, 2 label_feat, 3 memory, 4 face, 5 face_mask,
// 6 W1, 7 b1, 8 w2.  Output: alpha [B, M*S] then context [B, DF].
// ---------------------------------------------------------------------------
extern "C" void kernel_launch(void* const* d_in, const int* in_sizes, int n_in,
                              void* d_out, int out_size)
{
    const float* fc     = (const float*)d_in[0];
    const float* img    = (const float*)d_in[1];
    const float* label  = (const float*)d_in[2];
    const float* memory = (const float*)d_in[3];
    const float* face   = (const float*)d_in[4];
    const float* fmask  = (const float*)d_in[5];
    const float* W1     = (const float*)d_in[6];
    const float* b1     = (const float*)d_in[7];
    const float* w2     = (const float*)d_in[8];

    float* out   = (float*)d_out;
    float* alpha = out;                      // [B, M*S]
    float* ctx   = out + BB * MM * SS;       // [B, DF]

    gemm_pb_kernel<<<dim3(HH / BN, (BB * SS) / BM), 256>>>(face, fc, img, label, W1);
    pm_kernel<<<(BB * MM * HH) * 32 / 256, 256>>>(memory, W1, b1);
    e_kernel<<<dim3(SS / 8, BB), 256>>>(w2);
    softmax_kernel<<<BB, 1024>>>(fmask, alpha);
    context_kernel<<<BB, 512>>>(face, alpha, ctx);
}

// round 2
// speedup vs baseline: 1.2858x; 1.2858x over previous
#include <cuda_runtime.h>
#include <math_constants.h>

// Problem constants
#define BB    32
#define SS    512
#define MM    8
#define HH    512           // DIM2 / hidden
#define KBIG  1536          // face|fc|img (label folded into pm)
#define DIM1_ 2048
#define WCOLS 2560          // DIM1 + DIM2
#define EPSF  1e-5f

// Scratch (device globals — no allocation allowed)
__device__ float g_pb[(size_t)BB * SS * HH];   // part_base [B*S, H]
__device__ float g_pm[BB * MM * HH];           // part_mem + label_part + b1
__device__ float g_e [BB * MM * SS];           // logits e[b, m*S+s]

// ---------------------------------------------------------------------------
// f32x2 packed FMA helpers (sm_103a FFMA2)
// ---------------------------------------------------------------------------
__device__ __forceinline__ unsigned long long pk2(float x, float y) {
    unsigned long long r;
    asm("mov.b64 %0, {%1, %2};" : "=l"(r) : "f"(x), "f"(y));
    return r;
}
__device__ __forceinline__ void upk2(unsigned long long v, float& x, float& y) {
    asm("mov.b64 {%0, %1}, %2;" : "=f"(x), "=f"(y) : "l"(v));
}
__device__ __forceinline__ void ffma2(unsigned long long& d,
                                      unsigned long long a, unsigned long long b) {
    asm("fma.rn.f32x2 %0, %1, %2, %0;" : "+l"(d) : "l"(a), "l"(b));
}

// ---------------------------------------------------------------------------
// Kernel 1: part_base = base' @ W1a'^T, base' = [face | fc | img] (K = 1536).
// 128x128x16 double-buffered SGEMM, 8x8 microtile, packed-f32x2 inner loop.
// ---------------------------------------------------------------------------
#define BM 128
#define BN 128
#define BK 16
#define PADLD 132

__device__ __forceinline__ const float* base_ptr(
    const float* __restrict__ face, const float* __restrict__ fc,
    const float* __restrict__ img, int r, int d)
{
    const int f   = d >> 9;       // 0,1,2 (k-tile uniform)
    const int off = d & 511;
    if (f == 0) return face + (size_t)r * 512 + off;
    if (f == 1) return fc   + (size_t)r * 512 + off;
    return img + (size_t)r * 512 + off;
}

__global__ __launch_bounds__(256, 2)
void gemm_pb_kernel(const float* __restrict__ face, const float* __restrict__ fc,
                    const float* __restrict__ img,  const float* __restrict__ W1)
{
    __shared__ float As[2][BK][PADLD];
    __shared__ float Bs[2][BK][PADLD];

    const int tid     = threadIdx.x;
    const int rowBase = blockIdx.y * BM;
    const int colBase = blockIdx.x * BN;
    const int tx = tid & 15;
    const int ty = tid >> 4;

    const int r0 = tid >> 2;          // 0..63 (two passes cover 128 tile rows)
    const int kv = (tid & 3) * 4;     // float4 slot in 16-wide k tile

    unsigned long long acc2[8][4];
#pragma unroll
    for (int i = 0; i < 8; i++)
#pragma unroll
        for (int j = 0; j < 4; j++) acc2[i][j] = 0ull;

    // Preload tile 0
#pragma unroll
    for (int t = 0; t < 2; t++) {
        const int row = r0 + t * 64;
        const float4 va = *(const float4*)base_ptr(face, fc, img, rowBase + row, kv);
        As[0][kv + 0][row] = va.x; As[0][kv + 1][row] = va.y;
        As[0][kv + 2][row] = va.z; As[0][kv + 3][row] = va.w;
        const float4 vb = *(const float4*)&W1[(size_t)(colBase + row) * WCOLS + kv];
        Bs[0][kv + 0][row] = vb.x; Bs[0][kv + 1][row] = vb.y;
        Bs[0][kv + 2][row] = vb.z; Bs[0][kv + 3][row] = vb.w;
    }
    __syncthreads();

    const int NK = KBIG / BK;   // 96 k-tiles
    float4 na[2], nb[2];

    for (int kt = 0; kt < NK; kt++) {
        const int cur = kt & 1;

        if (kt + 1 < NK) {
            const int d0 = (kt + 1) * BK;
#pragma unroll
            for (int t = 0; t < 2; t++) {
                const int row = r0 + t * 64;
                na[t] = *(const float4*)base_ptr(face, fc, img, rowBase + row, d0 + kv);
                nb[t] = *(const float4*)&W1[(size_t)(colBase + row) * WCOLS + d0 + kv];
            }
        }

#pragma unroll
        for (int kk = 0; kk < BK; kk++) {
            float a[8], b[8];
            *(float4*)&a[0] = *(const float4*)&As[cur][kk][ty * 8];
            *(float4*)&a[4] = *(const float4*)&As[cur][kk][ty * 8 + 4];
            *(float4*)&b[0] = *(const float4*)&Bs[cur][kk][tx * 8];
            *(float4*)&b[4] = *(const float4*)&Bs[cur][kk][tx * 8 + 4];

            unsigned long long ad[8], bp[4];
#pragma unroll
            for (int i = 0; i < 8; i++) ad[i] = pk2(a[i], a[i]);
#pragma unroll
            for (int j = 0; j < 4; j++) bp[j] = pk2(b[2 * j], b[2 * j + 1]);

#pragma unroll
            for (int i = 0; i < 8; i++)
#pragma unroll
                for (int j = 0; j < 4; j++)
                    ffma2(acc2[i][j], ad[i], bp[j]);
        }

        if (kt + 1 < NK) {
            const int nxt = cur ^ 1;
#pragma unroll
            for (int t = 0; t < 2; t++) {
                const int row = r0 + t * 64;
                As[nxt][kv + 0][row] = na[t].x; As[nxt][kv + 1][row] = na[t].y;
                As[nxt][kv + 2][row] = na[t].z; As[nxt][kv + 3][row] = na[t].w;
                Bs[nxt][kv + 0][row] = nb[t].x; Bs[nxt][kv + 1][row] = nb[t].y;
                Bs[nxt][kv + 2][row] = nb[t].z; Bs[nxt][kv + 3][row] = nb[t].w;
            }
        }
        __syncthreads();
    }

    // Epilogue
#pragma unroll
    for (int i = 0; i < 8; i++) {
        float c[8];
#pragma unroll
        for (int j = 0; j < 4; j++) upk2(acc2[i][j], c[2 * j], c[2 * j + 1]);
        const size_t base = (size_t)(rowBase + ty * 8 + i) * HH + colBase + tx * 8;
        *(float4*)&g_pb[base]     = make_float4(c[0], c[1], c[2], c[3]);
        *(float4*)&g_pb[base + 4] = make_float4(c[4], c[5], c[6], c[7]);
    }
}

// ---------------------------------------------------------------------------
// Kernel 2: pm[b,m,h] = memory[b,m,:]·W1[h,2048:] + label[b,:]·W1[h,1536:2048] + b1[h]
// One warp per output; tiny, L2-resident.
// ---------------------------------------------------------------------------
__global__ __launch_bounds__(256)
void pm_kernel(const float* __restrict__ memory, const float* __restrict__ label,
               const float* __restrict__ W1, const float* __restrict__ b1)
{
    const int gw   = (blockIdx.x * blockDim.x + threadIdx.x) >> 5;  // 0 .. B*M*H-1
    const int lane = threadIdx.x & 31;
    const int h  = gw & (HH - 1);
    const int bm = gw >> 9;
    const int b  = bm >> 3;

    const float* __restrict__ wmem = W1 + (size_t)h * WCOLS + DIM1_;
    const float* __restrict__ wlab = W1 + (size_t)h * WCOLS + KBIG;
    const float* __restrict__ mrow = memory + (size_t)bm * HH;
    const float* __restrict__ lrow = label  + (size_t)b * 512;

    float acc = 0.f;
#pragma unroll 4
    for (int d = lane; d < HH; d += 32)
        acc = fmaf(wmem[d], mrow[d], fmaf(wlab[d], lrow[d], acc));
#pragma unroll
    for (int o = 16; o; o >>= 1) acc += __shfl_xor_sync(0xFFFFFFFFu, acc, o);
    if (lane == 0) g_pm[gw] = acc + b1[h];
}

// ---------------------------------------------------------------------------
// Kernel 3: e[b, m*S+s] = sum_h w2[h] * tanh(pb[b,s,h] + pm[b,m,h])
// ---------------------------------------------------------------------------
__global__ __launch_bounds__(256)
void e_kernel(const float* __restrict__ w2)
{
    __shared__ float pm_s[MM][HH];
    __shared__ float w2_s[HH];

    const int b   = blockIdx.y;
    const int tid = threadIdx.x;
    for (int i = tid; i < MM * HH; i += 256) ((float*)pm_s)[i] = g_pm[b * MM * HH + i];
    for (int i = tid; i < HH; i += 256)      w2_s[i] = w2[i];
    __syncthreads();

    const int warp = tid >> 5, lane = tid & 31;
    const int s = blockIdx.x * 8 + warp;
    const float* __restrict__ pb = g_pb + (size_t)(b * SS + s) * HH;

    float acc[MM];
#pragma unroll
    for (int m = 0; m < MM; m++) acc[m] = 0.f;

    for (int h = lane; h < HH; h += 32) {
        const float pbv = pb[h];
        const float w2v = w2_s[h];
#pragma unroll
        for (int m = 0; m < MM; m++)
            acc[m] = fmaf(w2v, tanhf(pbv + pm_s[m][h]), acc[m]);
    }
#pragma unroll
    for (int m = 0; m < MM; m++)
#pragma unroll
        for (int o = 16; o; o >>= 1) acc[m] += __shfl_xor_sync(0xFFFFFFFFu, acc[m], o);

    if (lane == 0) {
#pragma unroll
        for (int m = 0; m < MM; m++) g_e[b * MM * SS + m * SS + s] = acc[m];
    }
}

// ---------------------------------------------------------------------------
// Kernel 4: softmax over 4096, *mask, renorm by (masked_sum + EPS).
// ---------------------------------------------------------------------------
__global__ __launch_bounds__(1024)
void softmax_kernel(const float* __restrict__ face_mask, float* __restrict__ alpha)
{
    __shared__ float sred[32];
    const int b = blockIdx.x;
    const int tid = threadIdx.x;
    const int w = tid >> 5, l = tid & 31;
    const float* __restrict__ e = g_e + b * (MM * SS);

    float v[4];
    float mx = -CUDART_INF_F;
#pragma unroll
    for (int i = 0; i < 4; i++) { v[i] = e[tid + i * 1024]; mx = fmaxf(mx, v[i]); }

#pragma unroll
    for (int o = 16; o; o >>= 1) mx = fmaxf(mx, __shfl_xor_sync(0xFFFFFFFFu, mx, o));
    if (l == 0) sred[w] = mx;
    __syncthreads();
    if (tid < 32) {
        float t = sred[tid];
#pragma unroll
        for (int o = 16; o; o >>= 1) t = fmaxf(t, __shfl_xor_sync(0xFFFFFFFFu, t, o));
        if (tid == 0) sred[0] = t;
    }
    __syncthreads();
    mx = sred[0];
    __syncthreads();

    float sum = 0.f;
#pragma unroll
    for (int i = 0; i < 4; i++) { v[i] = __expf(v[i] - mx); sum += v[i]; }
#pragma unroll
    for (int o = 16; o; o >>= 1) sum += __shfl_xor_sync(0xFFFFFFFFu, sum, o);
    if (l == 0) sred[w] = sum;
    __syncthreads();
    if (tid < 32) {
        float t = sred[tid];
#pragma unroll
        for (int o = 16; o; o >>= 1) t += __shfl_xor_sync(0xFFFFFFFFu, t, o);
        if (tid == 0) sred[0] = t;
    }
    __syncthreads();
    const float Z = sred[0];
    __syncthreads();

    const float invZ = 1.f / Z;
    float msum = 0.f;
#pragma unroll
    for (int i = 0; i < 4; i++) {
        const int idx = tid + i * 1024;
        const float mk = face_mask[b * SS + (idx & 511)];
        v[i] = v[i] * invZ * mk;
        msum += v[i];
    }
#pragma unroll
    for (int o = 16; o; o >>= 1) msum += __shfl_xor_sync(0xFFFFFFFFu, msum, o);
    if (l == 0) sred[w] = msum;
    __syncthreads();
    if (tid < 32) {
        float t = sred[tid];
#pragma unroll
        for (int o = 16; o; o >>= 1) t += __shfl_xor_sync(0xFFFFFFFFu, t, o);
        if (tid == 0) sred[0] = t;
    }
    __syncthreads();
    const float inv = 1.f / (sred[0] + EPSF);

#pragma unroll
    for (int i = 0; i < 4; i++)
        alpha[b * (MM * SS) + tid + i * 1024] = v[i] * inv;
}

// ---------------------------------------------------------------------------
// Kernel 5: context[b,d] = sum_s (sum_m alpha[b,m,s]) * face[b,s,d]
// ---------------------------------------------------------------------------
__global__ __launch_bounds__(512)
void context_kernel(const float* __restrict__ face, const float* __restrict__ alpha,
                    float* __restrict__ ctx)
{
    __shared__ float asum[SS];
    const int b = blockIdx.x;
    const int tid = threadIdx.x;

    float a = 0.f;
#pragma unroll
    for (int m = 0; m < MM; m++) a += alpha[b * (MM * SS) + m * SS + tid];
    asum[tid] = a;
    __syncthreads();

    const float* __restrict__ fb = face + (size_t)b * SS * 512;
    float c0 = 0.f, c1 = 0.f, c2 = 0.f, c3 = 0.f;
    for (int s = 0; s < SS; s += 4) {
        c0 = fmaf(asum[s + 0], fb[(size_t)(s + 0) * 512 + tid], c0);
        c1 = fmaf(asum[s + 1], fb[(size_t)(s + 1) * 512 + tid], c1);
        c2 = fmaf(asum[s + 2], fb[(size_t)(s + 2) * 512 + tid], c2);
        c3 = fmaf(asum[s + 3], fb[(size_t)(s + 3) * 512 + tid], c3);
    }
    ctx[b * 512 + tid] = (c0 + c1) + (c2 + c3);
}

// ---------------------------------------------------------------------------
// Launch. Inputs: 0 fc, 1 img, 2 label, 3 memory, 4 face, 5 face_mask,
// 6 W1, 7 b1, 8 w2.  Output: alpha [B, M*S] then context [B, DF].
// ---------------------------------------------------------------------------
extern "C" void kernel_launch(void* const* d_in, const int* in_sizes, int n_in,
                              void* d_out, int out_size)
{
    const float* fc     = (const float*)d_in[0];
    const float* img    = (const float*)d_in[1];
    const float* label  = (const float*)d_in[2];
    const float* memory = (const float*)d_in[3];
    const float* face   = (const float*)d_in[4];
    const float* fmask  = (const float*)d_in[5];
    const float* W1     = (const float*)d_in[6];
    const float* b1     = (const float*)d_in[7];
    const float* w2     = (const float*)d_in[8];

    float* out   = (float*)d_out;
    float* alpha = out;                      // [B, M*S]
    float* ctx   = out + BB * MM * SS;       // [B, DF]

    gemm_pb_kernel<<<dim3(HH / BN, (BB * SS) / BM), 256>>>(face, fc, img, W1);
    pm_kernel<<<(BB * MM * HH) * 32 / 256, 256>>>(memory, label, W1, b1);
    e_kernel<<<dim3(SS / 8, BB), 256>>>(w2);
    softmax_kernel<<<BB, 1024>>>(fmask, alpha);
    context_kernel<<<BB, 512>>>(face, alpha, ctx);
}

// round 4
// speedup vs baseline: 1.6776x; 1.3046x over previous
#include <cuda_runtime.h>
#include <cuda_bf16.h>
#include <math_constants.h>
#include <cstdint>

// Problem constants
#define BB    32
#define SS    512
#define MM    8
#define HH    512
#define KBIG  1536          // face|fc|img (label folded into pm)
#define DIM1_ 2048
#define WCOLS 2560
#define EPSF  1e-5f

// GEMM tiling
#define GM 128
#define GN 128
#define KC 64                        // bf16 k per chunk = 128 B/row (SW128 atom)
#define NCH (KBIG / KC)              // 24 chunks
#define TILE_BYTES 16384             // 128 rows x 128 B
#define STAGE_BYTES (4 * TILE_BYTES) // Ahi | Alo | Bhi | Blo
#define DYN_SMEM (STAGE_BYTES + 1024)

// Scratch (device globals — no allocation allowed)
__device__ float g_pb[(size_t)BB * SS * HH];   // part_base [B*S, H]
__device__ float g_pm[BB * MM * HH];           // part_mem + label part + b1
__device__ float g_e [BB * MM * SS];           // logits e[b, m*S+s]

__device__ __forceinline__ uint32_t smem_u32(const void* p) {
    return (uint32_t)__cvta_generic_to_shared(p);
}

#define LDMX4(r, addr) \
    asm volatile("ldmatrix.sync.aligned.m8n8.x4.shared.b16 {%0,%1,%2,%3}, [%4];" \
        : "=r"((r)[0]), "=r"((r)[1]), "=r"((r)[2]), "=r"((r)[3]) : "r"(addr))

#define MMA16816(d, a, b0v, b1v) \
    asm volatile("mma.sync.aligned.m16n8k16.row.col.f32.bf16.bf16.f32 " \
        "{%0,%1,%2,%3}, {%4,%5,%6,%7}, {%8,%9}, {%0,%1,%2,%3};" \
        : "+f"((d)[0]), "+f"((d)[1]), "+f"((d)[2]), "+f"((d)[3]) \
        : "r"((a)[0]), "r"((a)[1]), "r"((a)[2]), "r"((a)[3]), "r"(b0v), "r"(b1v))

// fp32 -> bf16 hi/lo pair, packed as bf16x2 words
__device__ __forceinline__ void cvt_pair(float x, float y, uint32_t& hi, uint32_t& lo) {
    __nv_bfloat16 bx = __float2bfloat16_rn(x);
    __nv_bfloat16 by = __float2bfloat16_rn(y);
    __nv_bfloat16 lx = __float2bfloat16_rn(x - __bfloat162float(bx));
    __nv_bfloat16 ly = __float2bfloat16_rn(y - __bfloat162float(by));
    __nv_bfloat162 h; h.x = bx; h.y = by;
    __nv_bfloat162 l; l.x = lx; l.y = ly;
    hi = *(uint32_t*)&h; lo = *(uint32_t*)&l;
}

// Load one 64-k chunk of A (feature tensor) and B (W1) into the stage,
// fp32 -> bf16 hi/lo, SW128 swizzle. 256 threads.
__device__ __forceinline__ void load_chunk(char* stagep, int tid,
        const float* __restrict__ Asrc, int rowBase, int kqA,
        const float* __restrict__ W1, int colBase, int kqB)
{
#pragma unroll
    for (int i = 0; i < 8; i++) {               // A: 128 rows x 64 k
        const int v = tid + i * 256;
        const int row = v >> 4;
        const int c = (v & 15) * 4;
        const float4 a = *(const float4*)&Asrc[(size_t)(rowBase + row) * 512 + kqA + c];
        uint32_t h0, l0, h1, l1;
        cvt_pair(a.x, a.y, h0, l0);
        cvt_pair(a.z, a.w, h1, l1);
        const uint32_t off = row * 128 + c * 2;
        const uint32_t sw = off ^ ((off >> 3) & 0x70);
        *(uint2*)(stagep + sw)              = make_uint2(h0, h1);
        *(uint2*)(stagep + TILE_BYTES + sw) = make_uint2(l0, l1);
    }
#pragma unroll
    for (int i = 0; i < 8; i++) {               // B: 128 h-rows x 64 k
        const int v = tid + i * 256;
        const int row = v >> 4;
        const int c = (v & 15) * 4;
        const float4 b = *(const float4*)&W1[(size_t)(colBase + row) * WCOLS + kqB + c];
        uint32_t h0, l0, h1, l1;
        cvt_pair(b.x, b.y, h0, l0);
        cvt_pair(b.z, b.w, h1, l1);
        const uint32_t off = row * 128 + c * 2;
        const uint32_t sw = off ^ ((off >> 3) & 0x70);
        *(uint2*)(stagep + 2 * TILE_BYTES + sw) = make_uint2(h0, h1);
        *(uint2*)(stagep + 3 * TILE_BYTES + sw) = make_uint2(l0, l1);
    }
}

// ---------------------------------------------------------------------------
// Kernel 1: part_base via warp-level bf16 mma.sync, 3-product hi/lo split.
// Grid (4, 128), 256 threads, 2 CTAs/SM.
// ---------------------------------------------------------------------------
__global__ __launch_bounds__(256, 2)
void gemm_pb_mma(const float* __restrict__ face, const float* __restrict__ fc,
                 const float* __restrict__ img,  const float* __restrict__ W1)
{
    extern __shared__ char dynsmem[];
    const uint32_t dynaddr = smem_u32(dynsmem);
    const uint32_t sbase = (dynaddr + 1023) & ~1023u;
    char* stagep = dynsmem + (sbase - dynaddr);

    const int tid  = threadIdx.x;
    const int warp = tid >> 5;
    const int lane = tid & 31;
    const int mw = warp >> 2;            // 0..1 : m offset mw*64
    const int nw = warp & 3;             // 0..3 : n offset nw*32
    const int colBase = blockIdx.x * GN;
    const int rowBase = blockIdx.y * GM;

    // ldmatrix source rows (within the 128-row tile) for A and B fragments
    const int a_r  = lane & 15;          // row within m16 tile
    const int a_kh = lane >> 4;          // k half (16B chunk)
    const int b_r  = (lane & 7) + ((lane >> 4) << 3);  // row within n16 pair
    const int b_kh = (lane >> 3) & 1;

    float d[4][4][4];
#pragma unroll
    for (int i = 0; i < 4; i++)
#pragma unroll
        for (int j = 0; j < 4; j++)
#pragma unroll
            for (int q = 0; q < 4; q++) d[i][j][q] = 0.f;

    for (int kt = 0; kt < NCH; kt++) {
        const int f = kt >> 3;
        const float* src = (f == 0) ? face : (f == 1 ? fc : img);
        load_chunk(stagep, tid, src, rowBase, (kt & 7) * KC, W1, colBase, kt * KC);
        __syncthreads();

#pragma unroll
        for (int ks = 0; ks < 4; ks++) {
            const uint32_t kb = (ks * 2) * 16;

            uint32_t ah[4][4];
#pragma unroll
            for (int i = 0; i < 4; i++) {
                const uint32_t off = (uint32_t)(mw * 64 + i * 16 + a_r) * 128 + kb + a_kh * 16;
                LDMX4(ah[i], sbase + (off ^ ((off >> 3) & 0x70)));
            }
            uint32_t bh[2][4];
#pragma unroll
            for (int p = 0; p < 2; p++) {
                const uint32_t off = (uint32_t)(nw * 32 + p * 16 + b_r) * 128 + kb + b_kh * 16;
                LDMX4(bh[p], sbase + 2 * TILE_BYTES + (off ^ ((off >> 3) & 0x70)));
            }
            // hi * hi
#pragma unroll
            for (int i = 0; i < 4; i++)
#pragma unroll
                for (int p = 0; p < 2; p++) {
                    MMA16816(d[i][2 * p],     ah[i], bh[p][0], bh[p][1]);
                    MMA16816(d[i][2 * p + 1], ah[i], bh[p][2], bh[p][3]);
                }
            // hi * lo
            {
                uint32_t bl[2][4];
#pragma unroll
                for (int p = 0; p < 2; p++) {
                    const uint32_t off = (uint32_t)(nw * 32 + p * 16 + b_r) * 128 + kb + b_kh * 16;
                    LDMX4(bl[p], sbase + 3 * TILE_BYTES + (off ^ ((off >> 3) & 0x70)));
                }
#pragma unroll
                for (int i = 0; i < 4; i++)
#pragma unroll
                    for (int p = 0; p < 2; p++) {
                        MMA16816(d[i][2 * p],     ah[i], bl[p][0], bl[p][1]);
                        MMA16816(d[i][2 * p + 1], ah[i], bl[p][2], bl[p][3]);
                    }
            }
            // lo * hi
            {
                uint32_t al[4][4];
#pragma unroll
                for (int i = 0; i < 4; i++) {
                    const uint32_t off = (uint32_t)(mw * 64 + i * 16 + a_r) * 128 + kb + a_kh * 16;
                    LDMX4(al[i], sbase + TILE_BYTES + (off ^ ((off >> 3) & 0x70)));
                }
#pragma unroll
                for (int i = 0; i < 4; i++)
#pragma unroll
                    for (int p = 0; p < 2; p++) {
                        MMA16816(d[i][2 * p],     al[i], bh[p][0], bh[p][1]);
                        MMA16816(d[i][2 * p + 1], al[i], bh[p][2], bh[p][3]);
                    }
            }
        }
        __syncthreads();
    }

    // Epilogue: fragment layout -> g_pb
    const int r0 = rowBase + mw * 64 + (lane >> 2);
    const int c0 = colBase + nw * 32 + (lane & 3) * 2;
#pragma unroll
    for (int i = 0; i < 4; i++)
#pragma unroll
        for (int nt = 0; nt < 4; nt++) {
            const int row = r0 + i * 16;
            const int col = c0 + nt * 8;
            *(float2*)&g_pb[(size_t)row * HH + col]       = make_float2(d[i][nt][0], d[i][nt][1]);
            *(float2*)&g_pb[(size_t)(row + 8) * HH + col] = make_float2(d[i][nt][2], d[i][nt][3]);
        }
}

// ---------------------------------------------------------------------------
// Kernel 2: pm[b,m,h] = memory[b,m,:]·W1[h,2048:] + label[b,:]·W1[h,1536:2048] + b1[h]
// ---------------------------------------------------------------------------
__global__ __launch_bounds__(256)
void pm_kernel(const float* __restrict__ memory, const float* __restrict__ label,
               const float* __restrict__ W1, const float* __restrict__ b1)
{
    const int gw   = (blockIdx.x * blockDim.x + threadIdx.x) >> 5;
    const int lane = threadIdx.x & 31;
    const int h  = gw & (HH - 1);
    const int bm = gw >> 9;
    const int b  = bm >> 3;

    const float* __restrict__ wmem = W1 + (size_t)h * WCOLS + DIM1_;
    const float* __restrict__ wlab = W1 + (size_t)h * WCOLS + KBIG;
    const float* __restrict__ mrow = memory + (size_t)bm * HH;
    const float* __restrict__ lrow = label  + (size_t)b * 512;

    float acc = 0.f;
#pragma unroll 4
    for (int d = lane; d < HH; d += 32)
        acc = fmaf(wmem[d], mrow[d], fmaf(wlab[d], lrow[d], acc));
#pragma unroll
    for (int o = 16; o; o >>= 1) acc += __shfl_xor_sync(0xFFFFFFFFu, acc, o);
    if (lane == 0) g_pm[gw] = acc + b1[h];
}

// ---------------------------------------------------------------------------
// Kernel 3: e[b, m*S+s] = sum_h w2[h] * tanh(pb[b,s,h] + pm[b,m,h])
// ---------------------------------------------------------------------------
__global__ __launch_bounds__(256)
void e_kernel(const float* __restrict__ w2)
{
    __shared__ float pm_s[MM][HH];
    __shared__ float w2_s[HH];

    const int b   = blockIdx.y;
    const int tid = threadIdx.x;
    for (int i = tid; i < MM * HH; i += 256) ((float*)pm_s)[i] = g_pm[b * MM * HH + i];
    for (int i = tid; i < HH; i += 256)      w2_s[i] = w2[i];
    __syncthreads();

    const int warp = tid >> 5, lane = tid & 31;
    const int s = blockIdx.x * 8 + warp;
    const float* __restrict__ pb = g_pb + (size_t)(b * SS + s) * HH;

    float acc[MM];
#pragma unroll
    for (int m = 0; m < MM; m++) acc[m] = 0.f;

    for (int h = lane; h < HH; h += 32) {
        const float pbv = pb[h];
        const float w2v = w2_s[h];
#pragma unroll
        for (int m = 0; m < MM; m++)
            acc[m] = fmaf(w2v, tanhf(pbv + pm_s[m][h]), acc[m]);
    }
#pragma unroll
    for (int m = 0; m < MM; m++)
#pragma unroll
        for (int o = 16; o; o >>= 1) acc[m] += __shfl_xor_sync(0xFFFFFFFFu, acc[m], o);

    if (lane == 0) {
#pragma unroll
        for (int m = 0; m < MM; m++) g_e[b * MM * SS + m * SS + s] = acc[m];
    }
}

// ---------------------------------------------------------------------------
// Kernel 4: softmax over 4096, *mask, renorm by (masked_sum + EPS).
// ---------------------------------------------------------------------------
__global__ __launch_bounds__(1024)
void softmax_kernel(const float* __restrict__ face_mask, float* __restrict__ alpha)
{
    __shared__ float sred[32];
    const int b = blockIdx.x;
    const int tid = threadIdx.x;
    const int w = tid >> 5, l = tid & 31;
    const float* __restrict__ e = g_e + b * (MM * SS);

    float v[4];
    float mx = -CUDART_INF_F;
#pragma unroll
    for (int i = 0; i < 4; i++) { v[i] = e[tid + i * 1024]; mx = fmaxf(mx, v[i]); }

#pragma unroll
    for (int o = 16; o; o >>= 1) mx = fmaxf(mx, __shfl_xor_sync(0xFFFFFFFFu, mx, o));
    if (l == 0) sred[w] = mx;
    __syncthreads();
    if (tid < 32) {
        float t = sred[tid];
#pragma unroll
        for (int o = 16; o; o >>= 1) t = fmaxf(t, __shfl_xor_sync(0xFFFFFFFFu, t, o));
        if (tid == 0) sred[0] = t;
    }
    __syncthreads();
    mx = sred[0];
    __syncthreads();

    float sum = 0.f;
#pragma unroll
    for (int i = 0; i < 4; i++) { v[i] = __expf(v[i] - mx); sum += v[i]; }
#pragma unroll
    for (int o = 16; o; o >>= 1) sum += __shfl_xor_sync(0xFFFFFFFFu, sum, o);
    if (l == 0) sred[w] = sum;
    __syncthreads();
    if (tid < 32) {
        float t = sred[tid];
#pragma unroll
        for (int o = 16; o; o >>= 1) t += __shfl_xor_sync(0xFFFFFFFFu, t, o);
        if (tid == 0) sred[0] = t;
    }
    __syncthreads();
    const float Z = sred[0];
    __syncthreads();

    const float invZ = 1.f / Z;
    float msum = 0.f;
#pragma unroll
    for (int i = 0; i < 4; i++) {
        const int idx = tid + i * 1024;
        const float mk = face_mask[b * SS + (idx & 511)];
        v[i] = v[i] * invZ * mk;
        msum += v[i];
    }
#pragma unroll
    for (int o = 16; o; o >>= 1) msum += __shfl_xor_sync(0xFFFFFFFFu, msum, o);
    if (l == 0) sred[w] = msum;
    __syncthreads();
    if (tid < 32) {
        float t = sred[tid];
#pragma unroll
        for (int o = 16; o; o >>= 1) t += __shfl_xor_sync(0xFFFFFFFFu, t, o);
        if (tid == 0) sred[0] = t;
    }
    __syncthreads();
    const float inv = 1.f / (sred[0] + EPSF);

#pragma unroll
    for (int i = 0; i < 4; i++)
        alpha[b * (MM * SS) + tid + i * 1024] = v[i] * inv;
}

// ---------------------------------------------------------------------------
// Kernel 5: context[b,d] = sum_s (sum_m alpha[b,m,s]) * face[b,s,d]
// ---------------------------------------------------------------------------
__global__ __launch_bounds__(512)
void context_kernel(const float* __restrict__ face, const float* __restrict__ alpha,
                    float* __restrict__ ctx)
{
    __shared__ float asum[SS];
    const int b = blockIdx.x;
    const int tid = threadIdx.x;

    float a = 0.f;
#pragma unroll
    for (int m = 0; m < MM; m++) a += alpha[b * (MM * SS) + m * SS + tid];
    asum[tid] = a;
    __syncthreads();

    const float* __restrict__ fb = face + (size_t)b * SS * 512;
    float c0 = 0.f, c1 = 0.f, c2 = 0.f, c3 = 0.f;
    for (int s = 0; s < SS; s += 4) {
        c0 = fmaf(asum[s + 0], fb[(size_t)(s + 0) * 512 + tid], c0);
        c1 = fmaf(asum[s + 1], fb[(size_t)(s + 1) * 512 + tid], c1);
        c2 = fmaf(asum[s + 2], fb[(size_t)(s + 2) * 512 + tid], c2);
        c3 = fmaf(asum[s + 3], fb[(size_t)(s + 3) * 512 + tid], c3);
    }
    ctx[b * 512 + tid] = (c0 + c1) + (c2 + c3);
}

// ---------------------------------------------------------------------------
// Launch. Inputs: 0 fc, 1 img, 2 label, 3 memory, 4 face, 5 face_mask,
// 6 W1, 7 b1, 8 w2.  Output: alpha [B, M*S] then context [B, DF].
// ---------------------------------------------------------------------------
extern "C" void kernel_launch(void* const* d_in, const int* in_sizes, int n_in,
                              void* d_out, int out_size)
{
    const float* fc     = (const float*)d_in[0];
    const float* img    = (const float*)d_in[1];
    const float* label  = (const float*)d_in[2];
    const float* memory = (const float*)d_in[3];
    const float* face   = (const float*)d_in[4];
    const float* fmask  = (const float*)d_in[5];
    const float* W1     = (const float*)d_in[6];
    const float* b1     = (const float*)d_in[7];
    const float* w2     = (const float*)d_in[8];

    float* out   = (float*)d_out;
    float* alpha = out;                      // [B, M*S]
    float* ctx   = out + BB * MM * SS;       // [B, DF]

    cudaFuncSetAttribute(gemm_pb_mma, cudaFuncAttributeMaxDynamicSharedMemorySize, DYN_SMEM);

    gemm_pb_mma<<<dim3(HH / GN, (BB * SS) / GM), 256, DYN_SMEM>>>(face, fc, img, W1);
    pm_kernel<<<(BB * MM * HH) * 32 / 256, 256>>>(memory, label, W1, b1);
    e_kernel<<<dim3(SS / 8, BB), 256>>>(w2);
    softmax_kernel<<<BB, 1024>>>(fmask, alpha);
    context_kernel<<<BB, 512>>>(face, alpha, ctx);
}

// round 5
// speedup vs baseline: 2.6642x; 1.5882x over previous
#include <cuda_runtime.h>
#include <cuda_bf16.h>
#include <math_constants.h>
#include <cstdint>

// Problem constants
#define BB    32
#define SS    512
#define MM    8
#define HH    512
#define KBIG  1536          // face|fc|img (label folded into pm)
#define DIM1_ 2048
#define WCOLS 2560
#define EPSF  1e-5f

// GEMM tiling
#define GM 128
#define GN 128
#define KC 64                        // bf16 k per chunk = 128 B/row (SW128 atom)
#define NCH (KBIG / KC)              // 24 chunks
#define TILE_BYTES 16384             // 128 rows x 128 B
#define STAGE_BYTES (4 * TILE_BYTES) // Ahi | Alo | Bhi | Blo
#define DYN_SMEM (2 * STAGE_BYTES + 1024)

// Scratch (device globals — no allocation allowed)
__device__ float g_pb[(size_t)BB * SS * HH];   // part_base [B*S, H]
__device__ float g_pm[BB * MM * HH];           // part_mem + label part + b1
__device__ float g_e [BB * MM * SS];           // logits e[b, m*S+s]
// Pre-converted bf16 hi/lo operands
__device__ __nv_bfloat16 g_Ahi[(size_t)BB * SS * KBIG];
__device__ __nv_bfloat16 g_Alo[(size_t)BB * SS * KBIG];
__device__ __nv_bfloat16 g_Whi[HH * KBIG];
__device__ __nv_bfloat16 g_Wlo[HH * KBIG];

__device__ __forceinline__ uint32_t smem_u32(const void* p) {
    return (uint32_t)__cvta_generic_to_shared(p);
}

#define LDMX4(r, addr) \
    asm volatile("ldmatrix.sync.aligned.m8n8.x4.shared.b16 {%0,%1,%2,%3}, [%4];" \
        : "=r"((r)[0]), "=r"((r)[1]), "=r"((r)[2]), "=r"((r)[3]) : "r"(addr))

#define MMA16816(d, a, b0v, b1v) \
    asm volatile("mma.sync.aligned.m16n8k16.row.col.f32.bf16.bf16.f32 " \
        "{%0,%1,%2,%3}, {%4,%5,%6,%7}, {%8,%9}, {%0,%1,%2,%3};" \
        : "+f"((d)[0]), "+f"((d)[1]), "+f"((d)[2]), "+f"((d)[3]) \
        : "r"((a)[0]), "r"((a)[1]), "r"((a)[2]), "r"((a)[3]), "r"(b0v), "r"(b1v))

#define CPASYNC(dst, src) \
    asm volatile("cp.async.cg.shared.global [%0], [%1], 16;" :: "r"(dst), "l"(src))
#define CPCOMMIT() asm volatile("cp.async.commit_group;" ::: "memory")
#define CPWAIT1()  asm volatile("cp.async.wait_group 1;" ::: "memory")

// ---------------------------------------------------------------------------
// Kernel 0: one-shot fp32 -> bf16 hi/lo conversion of features and W1 slice.
// One float4 per thread.
// ---------------------------------------------------------------------------
#define FEAT4 ((size_t)BB * SS * KBIG / 4)   // 6291456
#define W4    (HH * KBIG / 4)                // 196608

__device__ __forceinline__ void cvt4(float4 v, uint2& hi, uint2& lo) {
    __nv_bfloat162 h0, h1, l0, l1;
    h0.x = __float2bfloat16_rn(v.x); h0.y = __float2bfloat16_rn(v.y);
    h1.x = __float2bfloat16_rn(v.z); h1.y = __float2bfloat16_rn(v.w);
    l0.x = __float2bfloat16_rn(v.x - __bfloat162float(h0.x));
    l0.y = __float2bfloat16_rn(v.y - __bfloat162float(h0.y));
    l1.x = __float2bfloat16_rn(v.z - __bfloat162float(h1.x));
    l1.y = __float2bfloat16_rn(v.w - __bfloat162float(h1.y));
    hi = make_uint2(*(uint32_t*)&h0, *(uint32_t*)&h1);
    lo = make_uint2(*(uint32_t*)&l0, *(uint32_t*)&l1);
}

__global__ __launch_bounds__(256)
void convert_kernel(const float* __restrict__ face, const float* __restrict__ fc,
                    const float* __restrict__ img,  const float* __restrict__ W1)
{
    size_t idx = (size_t)blockIdx.x * 256 + threadIdx.x;
    if (idx < FEAT4) {
        const size_t r  = idx / (KBIG / 4);
        const int    k  = (int)(idx % (KBIG / 4)) * 4;
        const int    f  = k >> 9;
        const float* src = ((f == 0) ? face : (f == 1 ? fc : img)) + r * 512 + (k & 511);
        uint2 hi, lo;
        cvt4(*(const float4*)src, hi, lo);
        *(uint2*)&g_Ahi[r * KBIG + k] = hi;
        *(uint2*)&g_Alo[r * KBIG + k] = lo;
    } else {
        idx -= FEAT4;
        if (idx >= W4) return;
        const int h = (int)(idx / (KBIG / 4));
        const int k = (int)(idx % (KBIG / 4)) * 4;
        uint2 hi, lo;
        cvt4(*(const float4*)&W1[(size_t)h * WCOLS + k], hi, lo);
        *(uint2*)&g_Whi[h * KBIG + k] = hi;
        *(uint2*)&g_Wlo[h * KBIG + k] = lo;
    }
}

// ---------------------------------------------------------------------------
// GEMM helpers
// ---------------------------------------------------------------------------
__device__ __forceinline__ void load_stage(uint32_t sb, int tid,
                                           int rowBase, int colBase, int kt)
{
#pragma unroll
    for (int i = 0; i < 4; i++) {
        const int v   = tid + i * 256;
        const int row = v >> 3;
        const int cs  = v & 7;
        const uint32_t off = (uint32_t)row * 128 + cs * 16;
        const uint32_t sw  = off ^ ((off >> 3) & 0x70);
        const size_t aoff = (size_t)(rowBase + row) * KBIG + kt * KC + cs * 8;
        const size_t boff = (size_t)(colBase + row) * KBIG + kt * KC + cs * 8;
        CPASYNC(sb + sw,                  (const char*)&g_Ahi[aoff]);
        CPASYNC(sb + TILE_BYTES + sw,     (const char*)&g_Alo[aoff]);
        CPASYNC(sb + 2 * TILE_BYTES + sw, (const char*)&g_Whi[boff]);
        CPASYNC(sb + 3 * TILE_BYTES + sw, (const char*)&g_Wlo[boff]);
    }
}

__device__ __forceinline__ void mma_stage(uint32_t sb, float (&d)[4][4][4],
        int mw, int nw, int a_r, int a_kh, int b_r, int b_kh)
{
#pragma unroll
    for (int ks = 0; ks < 4; ks++) {
        const uint32_t kb = (uint32_t)(ks * 2) * 16;

        uint32_t ah[4][4];
#pragma unroll
        for (int i = 0; i < 4; i++) {
            const uint32_t off = (uint32_t)(mw * 64 + i * 16 + a_r) * 128 + kb + a_kh * 16;
            LDMX4(ah[i], sb + (off ^ ((off >> 3) & 0x70)));
        }
        uint32_t bh[2][4];
#pragma unroll
        for (int p = 0; p < 2; p++) {
            const uint32_t off = (uint32_t)(nw * 32 + p * 16 + b_r) * 128 + kb + b_kh * 16;
            LDMX4(bh[p], sb + 2 * TILE_BYTES + (off ^ ((off >> 3) & 0x70)));
        }
        // hi * hi
#pragma unroll
        for (int i = 0; i < 4; i++)
#pragma unroll
            for (int p = 0; p < 2; p++) {
                MMA16816(d[i][2 * p],     ah[i], bh[p][0], bh[p][1]);
                MMA16816(d[i][2 * p + 1], ah[i], bh[p][2], bh[p][3]);
            }
        // hi * lo
        {
            uint32_t bl[2][4];
#pragma unroll
            for (int p = 0; p < 2; p++) {
                const uint32_t off = (uint32_t)(nw * 32 + p * 16 + b_r) * 128 + kb + b_kh * 16;
                LDMX4(bl[p], sb + 3 * TILE_BYTES + (off ^ ((off >> 3) & 0x70)));
            }
#pragma unroll
            for (int i = 0; i < 4; i++)
#pragma unroll
                for (int p = 0; p < 2; p++) {
                    MMA16816(d[i][2 * p],     ah[i], bl[p][0], bl[p][1]);
                    MMA16816(d[i][2 * p + 1], ah[i], bl[p][2], bl[p][3]);
                }
        }
        // lo * hi
        {
            uint32_t al[4][4];
#pragma unroll
            for (int i = 0; i < 4; i++) {
                const uint32_t off = (uint32_t)(mw * 64 + i * 16 + a_r) * 128 + kb + a_kh * 16;
                LDMX4(al[i], sb + TILE_BYTES + (off ^ ((off >> 3) & 0x70)));
            }
#pragma unroll
            for (int i = 0; i < 4; i++)
#pragma unroll
                for (int p = 0; p < 2; p++) {
                    MMA16816(d[i][2 * p],     al[i], bh[p][0], bh[p][1]);
                    MMA16816(d[i][2 * p + 1], al[i], bh[p][2], bh[p][3]);
                }
        }
    }
}

// ---------------------------------------------------------------------------
// Kernel 1: part_base via bf16 mma.sync, cp.async 2-stage pipeline.
// Grid (4, 128), 256 threads.
// ---------------------------------------------------------------------------
__global__ __launch_bounds__(256, 1)
void gemm_pb_mma(void)
{
    extern __shared__ char dynsmem[];
    const uint32_t dynaddr = smem_u32(dynsmem);
    const uint32_t sbase = (dynaddr + 1023) & ~1023u;

    const int tid  = threadIdx.x;
    const int warp = tid >> 5;
    const int lane = tid & 31;
    const int mw = warp >> 2;
    const int nw = warp & 3;
    const int colBase = blockIdx.x * GN;
    const int rowBase = blockIdx.y * GM;

    const int a_r  = lane & 15;
    const int a_kh = lane >> 4;
    const int b_r  = (lane & 7) + ((lane >> 4) << 3);
    const int b_kh = (lane >> 3) & 1;

    float d[4][4][4];
#pragma unroll
    for (int i = 0; i < 4; i++)
#pragma unroll
        for (int j = 0; j < 4; j++)
#pragma unroll
            for (int q = 0; q < 4; q++) d[i][j][q] = 0.f;

    load_stage(sbase, tid, rowBase, colBase, 0);
    CPCOMMIT();
    load_stage(sbase + STAGE_BYTES, tid, rowBase, colBase, 1);
    CPCOMMIT();

    for (int kt = 0; kt < NCH; kt++) {
        CPWAIT1();
        __syncthreads();
        mma_stage(sbase + (kt & 1) * STAGE_BYTES, d, mw, nw, a_r, a_kh, b_r, b_kh);
        __syncthreads();
        if (kt + 2 < NCH)
            load_stage(sbase + (kt & 1) * STAGE_BYTES, tid, rowBase, colBase, kt + 2);
        CPCOMMIT();
    }

    // Epilogue: fragment layout -> g_pb
    const int r0 = rowBase + mw * 64 + (lane >> 2);
    const int c0 = colBase + nw * 32 + (lane & 3) * 2;
#pragma unroll
    for (int i = 0; i < 4; i++)
#pragma unroll
        for (int nt = 0; nt < 4; nt++) {
            const int row = r0 + i * 16;
            const int col = c0 + nt * 8;
            *(float2*)&g_pb[(size_t)row * HH + col]       = make_float2(d[i][nt][0], d[i][nt][1]);
            *(float2*)&g_pb[(size_t)(row + 8) * HH + col] = make_float2(d[i][nt][2], d[i][nt][3]);
        }
}

// ---------------------------------------------------------------------------
// Kernel 2: pm[b,m,h] = memory[b,m,:]·W1[h,2048:] + label[b,:]·W1[h,1536:2048] + b1[h]
// ---------------------------------------------------------------------------
__global__ __launch_bounds__(256)
void pm_kernel(const float* __restrict__ memory, const float* __restrict__ label,
               const float* __restrict__ W1, const float* __restrict__ b1)
{
    const int gw   = (blockIdx.x * blockDim.x + threadIdx.x) >> 5;
    const int lane = threadIdx.x & 31;
    const int h  = gw & (HH - 1);
    const int bm = gw >> 9;
    const int b  = bm >> 3;

    const float* __restrict__ wmem = W1 + (size_t)h * WCOLS + DIM1_;
    const float* __restrict__ wlab = W1 + (size_t)h * WCOLS + KBIG;
    const float* __restrict__ mrow = memory + (size_t)bm * HH;
    const float* __restrict__ lrow = label  + (size_t)b * 512;

    float acc = 0.f;
#pragma unroll 4
    for (int d = lane; d < HH; d += 32)
        acc = fmaf(wmem[d], mrow[d], fmaf(wlab[d], lrow[d], acc));
#pragma unroll
    for (int o = 16; o; o >>= 1) acc += __shfl_xor_sync(0xFFFFFFFFu, acc, o);
    if (lane == 0) g_pm[gw] = acc + b1[h];
}

// ---------------------------------------------------------------------------
// Kernel 3: e[b, m*S+s] = sum_h w2[h] * tanh(pb[b,s,h] + pm[b,m,h])
// ---------------------------------------------------------------------------
__global__ __launch_bounds__(256)
void e_kernel(const float* __restrict__ w2)
{
    __shared__ float pm_s[MM][HH];
    __shared__ float w2_s[HH];

    const int b   = blockIdx.y;
    const int tid = threadIdx.x;
    for (int i = tid; i < MM * HH; i += 256) ((float*)pm_s)[i] = g_pm[b * MM * HH + i];
    for (int i = tid; i < HH; i += 256)      w2_s[i] = w2[i];
    __syncthreads();

    const int warp = tid >> 5, lane = tid & 31;
    const int s = blockIdx.x * 8 + warp;
    const float* __restrict__ pb = g_pb + (size_t)(b * SS + s) * HH;

    float acc[MM];
#pragma unroll
    for (int m = 0; m < MM; m++) acc[m] = 0.f;

    for (int h = lane; h < HH; h += 32) {
        const float pbv = pb[h];
        const float w2v = w2_s[h];
#pragma unroll
        for (int m = 0; m < MM; m++)
            acc[m] = fmaf(w2v, tanhf(pbv + pm_s[m][h]), acc[m]);
    }
#pragma unroll
    for (int m = 0; m < MM; m++)
#pragma unroll
        for (int o = 16; o; o >>= 1) acc[m] += __shfl_xor_sync(0xFFFFFFFFu, acc[m], o);

    if (lane == 0) {
#pragma unroll
        for (int m = 0; m < MM; m++) g_e[b * MM * SS + m * SS + s] = acc[m];
    }
}

// ---------------------------------------------------------------------------
// Kernel 4: softmax over 4096, *mask, renorm by (masked_sum + EPS).
// ---------------------------------------------------------------------------
__global__ __launch_bounds__(1024)
void softmax_kernel(const float* __restrict__ face_mask, float* __restrict__ alpha)
{
    __shared__ float sred[32];
    const int b = blockIdx.x;
    const int tid = threadIdx.x;
    const int w = tid >> 5, l = tid & 31;
    const float* __restrict__ e = g_e + b * (MM * SS);

    float v[4];
    float mx = -CUDART_INF_F;
#pragma unroll
    for (int i = 0; i < 4; i++) { v[i] = e[tid + i * 1024]; mx = fmaxf(mx, v[i]); }

#pragma unroll
    for (int o = 16; o; o >>= 1) mx = fmaxf(mx, __shfl_xor_sync(0xFFFFFFFFu, mx, o));
    if (l == 0) sred[w] = mx;
    __syncthreads();
    if (tid < 32) {
        float t = sred[tid];
#pragma unroll
        for (int o = 16; o; o >>= 1) t = fmaxf(t, __shfl_xor_sync(0xFFFFFFFFu, t, o));
        if (tid == 0) sred[0] = t;
    }
    __syncthreads();
    mx = sred[0];
    __syncthreads();

    float sum = 0.f;
#pragma unroll
    for (int i = 0; i < 4; i++) { v[i] = __expf(v[i] - mx); sum += v[i]; }
#pragma unroll
    for (int o = 16; o; o >>= 1) sum += __shfl_xor_sync(0xFFFFFFFFu, sum, o);
    if (l == 0) sred[w] = sum;
    __syncthreads();
    if (tid < 32) {
        float t = sred[tid];
#pragma unroll
        for (int o = 16; o; o >>= 1) t += __shfl_xor_sync(0xFFFFFFFFu, t, o);
        if (tid == 0) sred[0] = t;
    }
    __syncthreads();
    const float Z = sred[0];
    __syncthreads();

    const float invZ = 1.f / Z;
    float msum = 0.f;
#pragma unroll
    for (int i = 0; i < 4; i++) {
        const int idx = tid + i * 1024;
        const float mk = face_mask[b * SS + (idx & 511)];
        v[i] = v[i] * invZ * mk;
        msum += v[i];
    }
#pragma unroll
    for (int o = 16; o; o >>= 1) msum += __shfl_xor_sync(0xFFFFFFFFu, msum, o);
    if (l == 0) sred[w] = msum;
    __syncthreads();
    if (tid < 32) {
        float t = sred[tid];
#pragma unroll
        for (int o = 16; o; o >>= 1) t += __shfl_xor_sync(0xFFFFFFFFu, t, o);
        if (tid == 0) sred[0] = t;
    }
    __syncthreads();
    const float inv = 1.f / (sred[0] + EPSF);

#pragma unroll
    for (int i = 0; i < 4; i++)
        alpha[b * (MM * SS) + tid + i * 1024] = v[i] * inv;
}

// ---------------------------------------------------------------------------
// Kernel 5: context[b,d] = sum_s (sum_m alpha[b,m,s]) * face[b,s,d]
// ---------------------------------------------------------------------------
__global__ __launch_bounds__(512)
void context_kernel(const float* __restrict__ face, const float* __restrict__ alpha,
                    float* __restrict__ ctx)
{
    __shared__ float asum[SS];
    const int b = blockIdx.x;
    const int tid = threadIdx.x;

    float a = 0.f;
#pragma unroll
    for (int m = 0; m < MM; m++) a += alpha[b * (MM * SS) + m * SS + tid];
    asum[tid] = a;
    __syncthreads();

    const float* __restrict__ fb = face + (size_t)b * SS * 512;
    float c0 = 0.f, c1 = 0.f, c2 = 0.f, c3 = 0.f;
    for (int s = 0; s < SS; s += 4) {
        c0 = fmaf(asum[s + 0], fb[(size_t)(s + 0) * 512 + tid], c0);
        c1 = fmaf(asum[s + 1], fb[(size_t)(s + 1) * 512 + tid], c1);
        c2 = fmaf(asum[s + 2], fb[(size_t)(s + 2) * 512 + tid], c2);
        c3 = fmaf(asum[s + 3], fb[(size_t)(s + 3) * 512 + tid], c3);
    }
    ctx[b * 512 + tid] = (c0 + c1) + (c2 + c3);
}

// ---------------------------------------------------------------------------
// Launch. Inputs: 0 fc, 1 img, 2 label, 3 memory, 4 face, 5 face_mask,
// 6 W1, 7 b1, 8 w2.  Output: alpha [B, M*S] then context [B, DF].
// ---------------------------------------------------------------------------
extern "C" void kernel_launch(void* const* d_in, const int* in_sizes, int n_in,
                              void* d_out, int out_size)
{
    const float* fc     = (const float*)d_in[0];
    const float* img    = (const float*)d_in[1];
    const float* label  = (const float*)d_in[2];
    const float* memory = (const float*)d_in[3];
    const float* face   = (const float*)d_in[4];
    const float* fmask  = (const float*)d_in[5];
    const float* W1     = (const float*)d_in[6];
    const float* b1     = (const float*)d_in[7];
    const float* w2     = (const float*)d_in[8];

    float* out   = (float*)d_out;
    float* alpha = out;                      // [B, M*S]
    float* ctx   = out + BB * MM * SS;       // [B, DF]

    cudaFuncSetAttribute(gemm_pb_mma, cudaFuncAttributeMaxDynamicSharedMemorySize, DYN_SMEM);

    const int cvt_blocks = (int)((FEAT4 + W4 + 255) / 256);
    convert_kernel<<<cvt_blocks, 256>>>(face, fc, img, W1);
    gemm_pb_mma<<<dim3(HH / GN, (BB * SS) / GM), 256, DYN_SMEM>>>();
    pm_kernel<<<(BB * MM * HH) * 32 / 256, 256>>>(memory, label, W1, b1);
    e_kernel<<<dim3(SS / 8, BB), 256>>>(w2);
    softmax_kernel<<<BB, 1024>>>(fmask, alpha);
    context_kernel<<<BB, 512>>>(face, alpha, ctx);
}

// round 6
// speedup vs baseline: 2.7905x; 1.0474x over previous
#include <cuda_runtime.h>
#include <cuda_bf16.h>
#include <math_constants.h>
#include <cstdint>

// Problem constants
#define BB    32
#define SS    512
#define MM    8
#define HH    512
#define KBIG  1536          // face|fc|img (label folded into pm)
#define DIM1_ 2048
#define WCOLS 2560
#define EPSF  1e-5f

// GEMM tiling: CTA 128x256, warp tile 64x64, 8 warps
#define GM 128
#define GN 256
#define KC 64                        // bf16 k per chunk = 128 B/row
#define NCH (KBIG / KC)              // 24 chunks
#define A_TILE 16384                 // 128 rows x 128 B
#define B_TILE 32768                 // 256 rows x 128 B
#define STAGE_BYTES (2 * A_TILE + 2 * B_TILE)   // Ahi|Alo|Bhi|Blo = 96 KB
#define DYN_SMEM (2 * STAGE_BYTES + 1024)

// Scratch (device globals — no allocation allowed)
__device__ float g_pb[(size_t)BB * SS * HH];   // part_base [B*S, H]
__device__ float g_pm[BB * MM * HH];           // part_mem + label part + b1
__device__ float g_e [BB * MM * SS];           // logits e[b, m*S+s]
// Pre-converted bf16 hi/lo operands
__device__ __nv_bfloat16 g_Ahi[(size_t)BB * SS * KBIG];
__device__ __nv_bfloat16 g_Alo[(size_t)BB * SS * KBIG];
__device__ __nv_bfloat16 g_Whi[HH * KBIG];
__device__ __nv_bfloat16 g_Wlo[HH * KBIG];

__device__ __forceinline__ uint32_t smem_u32(const void* p) {
    return (uint32_t)__cvta_generic_to_shared(p);
}

#define LDMX4(r, addr) \
    asm volatile("ldmatrix.sync.aligned.m8n8.x4.shared.b16 {%0,%1,%2,%3}, [%4];" \
        : "=r"((r)[0]), "=r"((r)[1]), "=r"((r)[2]), "=r"((r)[3]) : "r"(addr))

#define MMA16816(d, a, b0v, b1v) \
    asm volatile("mma.sync.aligned.m16n8k16.row.col.f32.bf16.bf16.f32 " \
        "{%0,%1,%2,%3}, {%4,%5,%6,%7}, {%8,%9}, {%0,%1,%2,%3};" \
        : "+f"((d)[0]), "+f"((d)[1]), "+f"((d)[2]), "+f"((d)[3]) \
        : "r"((a)[0]), "r"((a)[1]), "r"((a)[2]), "r"((a)[3]), "r"(b0v), "r"(b1v))

#define CPASYNC(dst, src) \
    asm volatile("cp.async.cg.shared.global [%0], [%1], 16;" :: "r"(dst), "l"(src))
#define CPCOMMIT() asm volatile("cp.async.commit_group;" ::: "memory")
#define CPWAIT1()  asm volatile("cp.async.wait_group 1;" ::: "memory")

// Fast, accurate tanh: 2 MUFU (EX2 + RCP) + few FMA. err ~1e-6.
__device__ __forceinline__ float fast_tanh(float x) {
    const float e = __expf(2.0f * x);
    return 1.0f - __fdividef(2.0f, e + 1.0f);
}

// ---------------------------------------------------------------------------
// Kernel 0: one-shot fp32 -> bf16 hi/lo conversion of features and W1 slice.
// ---------------------------------------------------------------------------
#define FEAT4 ((size_t)BB * SS * KBIG / 4)   // 6291456
#define W4    (HH * KBIG / 4)                // 196608

__device__ __forceinline__ void cvt4(float4 v, uint2& hi, uint2& lo) {
    __nv_bfloat162 h0, h1, l0, l1;
    h0.x = __float2bfloat16_rn(v.x); h0.y = __float2bfloat16_rn(v.y);
    h1.x = __float2bfloat16_rn(v.z); h1.y = __float2bfloat16_rn(v.w);
    l0.x = __float2bfloat16_rn(v.x - __bfloat162float(h0.x));
    l0.y = __float2bfloat16_rn(v.y - __bfloat162float(h0.y));
    l1.x = __float2bfloat16_rn(v.z - __bfloat162float(h1.x));
    l1.y = __float2bfloat16_rn(v.w - __bfloat162float(h1.y));
    hi = make_uint2(*(uint32_t*)&h0, *(uint32_t*)&h1);
    lo = make_uint2(*(uint32_t*)&l0, *(uint32_t*)&l1);
}

__global__ __launch_bounds__(256)
void convert_kernel(const float* __restrict__ face, const float* __restrict__ fc,
                    const float* __restrict__ img,  const float* __restrict__ W1)
{
    size_t idx = (size_t)blockIdx.x * 256 + threadIdx.x;
    if (idx < FEAT4) {
        const size_t r  = idx / (KBIG / 4);
        const int    k  = (int)(idx % (KBIG / 4)) * 4;
        const int    f  = k >> 9;
        const float* src = ((f == 0) ? face : (f == 1 ? fc : img)) + r * 512 + (k & 511);
        uint2 hi, lo;
        cvt4(*(const float4*)src, hi, lo);
        *(uint2*)&g_Ahi[r * KBIG + k] = hi;
        *(uint2*)&g_Alo[r * KBIG + k] = lo;
    } else {
        idx -= FEAT4;
        if (idx >= W4) return;
        const int h = (int)(idx / (KBIG / 4));
        const int k = (int)(idx % (KBIG / 4)) * 4;
        uint2 hi, lo;
        cvt4(*(const float4*)&W1[(size_t)h * WCOLS + k], hi, lo);
        *(uint2*)&g_Whi[h * KBIG + k] = hi;
        *(uint2*)&g_Wlo[h * KBIG + k] = lo;
    }
}

// ---------------------------------------------------------------------------
// GEMM helpers (stage layout: Ahi 0 | Alo 16K | Bhi 32K | Blo 64K)
// ---------------------------------------------------------------------------
__device__ __forceinline__ void load_stage(uint32_t sb, int tid,
                                           int rowBase, int colBase, int kt)
{
#pragma unroll
    for (int i = 0; i < 4; i++) {              // A: 128 rows
        const int v   = tid + i * 256;
        const int row = v >> 3;
        const int cs  = v & 7;
        const uint32_t off = (uint32_t)row * 128 + cs * 16;
        const uint32_t sw  = off ^ ((off >> 3) & 0x70);
        const size_t aoff = (size_t)(rowBase + row) * KBIG + kt * KC + cs * 8;
        CPASYNC(sb + sw,          (const char*)&g_Ahi[aoff]);
        CPASYNC(sb + A_TILE + sw, (const char*)&g_Alo[aoff]);
    }
#pragma unroll
    for (int i = 0; i < 8; i++) {              // B: 256 rows
        const int v   = tid + i * 256;
        const int row = v >> 3;
        const int cs  = v & 7;
        const uint32_t off = (uint32_t)row * 128 + cs * 16;
        const uint32_t sw  = off ^ ((off >> 3) & 0x70);
        const size_t boff = (size_t)(colBase + row) * KBIG + kt * KC + cs * 8;
        CPASYNC(sb + 2 * A_TILE + sw,          (const char*)&g_Whi[boff]);
        CPASYNC(sb + 2 * A_TILE + B_TILE + sw, (const char*)&g_Wlo[boff]);
    }
}

__device__ __forceinline__ void mma_stage(uint32_t sb, float (&d)[4][8][4],
        int mw, int nw, int a_r, int a_kh, int b_r, int b_kh)
{
#pragma unroll
    for (int ks = 0; ks < 4; ks++) {
        const uint32_t kb = (uint32_t)(ks * 2) * 16;

        uint32_t ah[4][4];
#pragma unroll
        for (int i = 0; i < 4; i++) {
            const uint32_t off = (uint32_t)(mw * 64 + i * 16 + a_r) * 128 + kb + a_kh * 16;
            LDMX4(ah[i], sb + (off ^ ((off >> 3) & 0x70)));
        }
        uint32_t bh[4][4];
#pragma unroll
        for (int p = 0; p < 4; p++) {
            const uint32_t off = (uint32_t)(nw * 64 + p * 16 + b_r) * 128 + kb + b_kh * 16;
            LDMX4(bh[p], sb + 2 * A_TILE + (off ^ ((off >> 3) & 0x70)));
        }
        // hi * hi
#pragma unroll
        for (int i = 0; i < 4; i++)
#pragma unroll
            for (int p = 0; p < 4; p++) {
                MMA16816(d[i][2 * p],     ah[i], bh[p][0], bh[p][1]);
                MMA16816(d[i][2 * p + 1], ah[i], bh[p][2], bh[p][3]);
            }
        // hi * lo
        {
            uint32_t bl[4][4];
#pragma unroll
            for (int p = 0; p < 4; p++) {
                const uint32_t off = (uint32_t)(nw * 64 + p * 16 + b_r) * 128 + kb + b_kh * 16;
                LDMX4(bl[p], sb + 2 * A_TILE + B_TILE + (off ^ ((off >> 3) & 0x70)));
            }
#pragma unroll
            for (int i = 0; i < 4; i++)
#pragma unroll
                for (int p = 0; p < 4; p++) {
                    MMA16816(d[i][2 * p],     ah[i], bl[p][0], bl[p][1]);
                    MMA16816(d[i][2 * p + 1], ah[i], bl[p][2], bl[p][3]);
                }
        }
        // lo * hi
        {
            uint32_t al[4][4];
#pragma unroll
            for (int i = 0; i < 4; i++) {
                const uint32_t off = (uint32_t)(mw * 64 + i * 16 + a_r) * 128 + kb + a_kh * 16;
                LDMX4(al[i], sb + A_TILE + (off ^ ((off >> 3) & 0x70)));
            }
#pragma unroll
            for (int i = 0; i < 4; i++)
#pragma unroll
                for (int p = 0; p < 4; p++) {
                    MMA16816(d[i][2 * p],     al[i], bh[p][0], bh[p][1]);
                    MMA16816(d[i][2 * p + 1], al[i], bh[p][2], bh[p][3]);
                }
        }
    }
}

// ---------------------------------------------------------------------------
// Kernel 1: part_base via bf16 mma.sync, cp.async 2-stage pipeline.
// Grid (2, 128), 256 threads; warp tile 64x64.
// ---------------------------------------------------------------------------
__global__ __launch_bounds__(256, 1)
void gemm_pb_mma(void)
{
    extern __shared__ char dynsmem[];
    const uint32_t dynaddr = smem_u32(dynsmem);
    const uint32_t sbase = (dynaddr + 1023) & ~1023u;

    const int tid  = threadIdx.x;
    const int warp = tid >> 5;
    const int lane = tid & 31;
    const int mw = warp >> 2;            // 0..1 : m offset mw*64
    const int nw = warp & 3;             // 0..3 : n offset nw*64
    const int colBase = blockIdx.x * GN;
    const int rowBase = blockIdx.y * GM;

    const int a_r  = lane & 15;
    const int a_kh = lane >> 4;
    const int b_r  = (lane & 7) + ((lane >> 4) << 3);
    const int b_kh = (lane >> 3) & 1;

    float d[4][8][4];
#pragma unroll
    for (int i = 0; i < 4; i++)
#pragma unroll
        for (int j = 0; j < 8; j++)
#pragma unroll
            for (int q = 0; q < 4; q++) d[i][j][q] = 0.f;

    load_stage(sbase, tid, rowBase, colBase, 0);
    CPCOMMIT();
    load_stage(sbase + STAGE_BYTES, tid, rowBase, colBase, 1);
    CPCOMMIT();

    for (int kt = 0; kt < NCH; kt++) {
        CPWAIT1();
        __syncthreads();
        mma_stage(sbase + (kt & 1) * STAGE_BYTES, d, mw, nw, a_r, a_kh, b_r, b_kh);
        __syncthreads();
        if (kt + 2 < NCH)
            load_stage(sbase + (kt & 1) * STAGE_BYTES, tid, rowBase, colBase, kt + 2);
        CPCOMMIT();
    }

    // Epilogue: fragment layout -> g_pb
    const int r0 = rowBase + mw * 64 + (lane >> 2);
    const int c0 = colBase + nw * 64 + (lane & 3) * 2;
#pragma unroll
    for (int i = 0; i < 4; i++)
#pragma unroll
        for (int nt = 0; nt < 8; nt++) {
            const int row = r0 + i * 16;
            const int col = c0 + nt * 8;
            *(float2*)&g_pb[(size_t)row * HH + col]       = make_float2(d[i][nt][0], d[i][nt][1]);
            *(float2*)&g_pb[(size_t)(row + 8) * HH + col] = make_float2(d[i][nt][2], d[i][nt][3]);
        }
}

// ---------------------------------------------------------------------------
// Kernel 2: pm[b,m,h] = memory[b,m,:]·W1[h,2048:] + label[b,:]·W1[h,1536:2048] + b1[h]
// ---------------------------------------------------------------------------
__global__ __launch_bounds__(256)
void pm_kernel(const float* __restrict__ memory, const float* __restrict__ label,
               const float* __restrict__ W1, const float* __restrict__ b1)
{
    const int gw   = (blockIdx.x * blockDim.x + threadIdx.x) >> 5;
    const int lane = threadIdx.x & 31;
    const int h  = gw & (HH - 1);
    const int bm = gw >> 9;
    const int b  = bm >> 3;

    const float* __restrict__ wmem = W1 + (size_t)h * WCOLS + DIM1_;
    const float* __restrict__ wlab = W1 + (size_t)h * WCOLS + KBIG;
    const float* __restrict__ mrow = memory + (size_t)bm * HH;
    const float* __restrict__ lrow = label  + (size_t)b * 512;

    float acc = 0.f;
#pragma unroll 4
    for (int d = lane; d < HH; d += 32)
        acc = fmaf(wmem[d], mrow[d], fmaf(wlab[d], lrow[d], acc));
#pragma unroll
    for (int o = 16; o; o >>= 1) acc += __shfl_xor_sync(0xFFFFFFFFu, acc, o);
    if (lane == 0) g_pm[gw] = acc + b1[h];
}

// ---------------------------------------------------------------------------
// Kernel 3: e[b, m*S+s] = sum_h w2[h] * tanh(pb[b,s,h] + pm[b,m,h])
// ---------------------------------------------------------------------------
__global__ __launch_bounds__(256)
void e_kernel(const float* __restrict__ w2)
{
    __shared__ float pm_s[MM][HH];
    __shared__ float w2_s[HH];

    const int b   = blockIdx.y;
    const int tid = threadIdx.x;
    for (int i = tid; i < MM * HH; i += 256) ((float*)pm_s)[i] = g_pm[b * MM * HH + i];
    for (int i = tid; i < HH; i += 256)      w2_s[i] = w2[i];
    __syncthreads();

    const int warp = tid >> 5, lane = tid & 31;
    const int s = blockIdx.x * 8 + warp;
    const float* __restrict__ pb = g_pb + (size_t)(b * SS + s) * HH;

    float acc[MM];
#pragma unroll
    for (int m = 0; m < MM; m++) acc[m] = 0.f;

    for (int h = lane; h < HH; h += 32) {
        const float pbv = pb[h];
        const float w2v = w2_s[h];
#pragma unroll
        for (int m = 0; m < MM; m++)
            acc[m] = fmaf(w2v, fast_tanh(pbv + pm_s[m][h]), acc[m]);
    }
#pragma unroll
    for (int m = 0; m < MM; m++)
#pragma unroll
        for (int o = 16; o; o >>= 1) acc[m] += __shfl_xor_sync(0xFFFFFFFFu, acc[m], o);

    if (lane == 0) {
#pragma unroll
        for (int m = 0; m < MM; m++) g_e[b * MM * SS + m * SS + s] = acc[m];
    }
}

// ---------------------------------------------------------------------------
// Kernel 4: softmax over 4096, *mask, renorm by (masked_sum + EPS).
// ---------------------------------------------------------------------------
__global__ __launch_bounds__(1024)
void softmax_kernel(const float* __restrict__ face_mask, float* __restrict__ alpha)
{
    __shared__ float sred[32];
    const int b = blockIdx.x;
    const int tid = threadIdx.x;
    const int w = tid >> 5, l = tid & 31;
    const float* __restrict__ e = g_e + b * (MM * SS);

    float v[4];
    float mx = -CUDART_INF_F;
#pragma unroll
    for (int i = 0; i < 4; i++) { v[i] = e[tid + i * 1024]; mx = fmaxf(mx, v[i]); }

#pragma unroll
    for (int o = 16; o; o >>= 1) mx = fmaxf(mx, __shfl_xor_sync(0xFFFFFFFFu, mx, o));
    if (l == 0) sred[w] = mx;
    __syncthreads();
    if (tid < 32) {
        float t = sred[tid];
#pragma unroll
        for (int o = 16; o; o >>= 1) t = fmaxf(t, __shfl_xor_sync(0xFFFFFFFFu, t, o));
        if (tid == 0) sred[0] = t;
    }
    __syncthreads();
    mx = sred[0];
    __syncthreads();

    float sum = 0.f;
#pragma unroll
    for (int i = 0; i < 4; i++) { v[i] = __expf(v[i] - mx); sum += v[i]; }
#pragma unroll
    for (int o = 16; o; o >>= 1) sum += __shfl_xor_sync(0xFFFFFFFFu, sum, o);
    if (l == 0) sred[w] = sum;
    __syncthreads();
    if (tid < 32) {
        float t = sred[tid];
#pragma unroll
        for (int o = 16; o; o >>= 1) t += __shfl_xor_sync(0xFFFFFFFFu, t, o);
        if (tid == 0) sred[0] = t;
    }
    __syncthreads();
    const float Z = sred[0];
    __syncthreads();

    const float invZ = 1.f / Z;
    float msum = 0.f;
#pragma unroll
    for (int i = 0; i < 4; i++) {
        const int idx = tid + i * 1024;
        const float mk = face_mask[b * SS + (idx & 511)];
        v[i] = v[i] * invZ * mk;
        msum += v[i];
    }
#pragma unroll
    for (int o = 16; o; o >>= 1) msum += __shfl_xor_sync(0xFFFFFFFFu, msum, o);
    if (l == 0) sred[w] = msum;
    __syncthreads();
    if (tid < 32) {
        float t = sred[tid];
#pragma unroll
        for (int o = 16; o; o >>= 1) t += __shfl_xor_sync(0xFFFFFFFFu, t, o);
        if (tid == 0) sred[0] = t;
    }
    __syncthreads();
    const float inv = 1.f / (sred[0] + EPSF);

#pragma unroll
    for (int i = 0; i < 4; i++)
        alpha[b * (MM * SS) + tid + i * 1024] = v[i] * inv;
}

// ---------------------------------------------------------------------------
// Kernel 5: context[b,d] = sum_s (sum_m alpha[b,m,s]) * face[b,s,d]
// ---------------------------------------------------------------------------
__global__ __launch_bounds__(512)
void context_kernel(const float* __restrict__ face, const float* __restrict__ alpha,
                    float* __restrict__ ctx)
{
    __shared__ float asum[SS];
    const int b = blockIdx.x;
    const int tid = threadIdx.x;

    float a = 0.f;
#pragma unroll
    for (int m = 0; m < MM; m++) a += alpha[b * (MM * SS) + m * SS + tid];
    asum[tid] = a;
    __syncthreads();

    const float* __restrict__ fb = face + (size_t)b * SS * 512;
    float c0 = 0.f, c1 = 0.f, c2 = 0.f, c3 = 0.f;
    for (int s = 0; s < SS; s += 4) {
        c0 = fmaf(asum[s + 0], fb[(size_t)(s + 0) * 512 + tid], c0);
        c1 = fmaf(asum[s + 1], fb[(size_t)(s + 1) * 512 + tid], c1);
        c2 = fmaf(asum[s + 2], fb[(size_t)(s + 2) * 512 + tid], c2);
        c3 = fmaf(asum[s + 3], fb[(size_t)(s + 3) * 512 + tid], c3);
    }
    ctx[b * 512 + tid] = (c0 + c1) + (c2 + c3);
}

// ---------------------------------------------------------------------------
// Launch. Inputs: 0 fc, 1 img, 2 label, 3 memory, 4 face, 5 face_mask,
// 6 W1, 7 b1, 8 w2.  Output: alpha [B, M*S] then context [B, DF].
// ---------------------------------------------------------------------------
extern "C" void kernel_launch(void* const* d_in, const int* in_sizes, int n_in,
                              void* d_out, int out_size)
{
    const float* fc     = (const float*)d_in[0];
    const float* img    = (const float*)d_in[1];
    const float* label  = (const float*)d_in[2];
    const float* memory = (const float*)d_in[3];
    const float* face   = (const float*)d_in[4];
    const float* fmask  = (const float*)d_in[5];
    const float* W1     = (const float*)d_in[6];
    const float* b1     = (const float*)d_in[7];
    const float* w2     = (const float*)d_in[8];

    float* out   = (float*)d_out;
    float* alpha = out;                      // [B, M*S]
    float* ctx   = out + BB * MM * SS;       // [B, DF]

    cudaFuncSetAttribute(gemm_pb_mma, cudaFuncAttributeMaxDynamicSharedMemorySize, DYN_SMEM);

    const int cvt_blocks = (int)((FEAT4 + W4 + 255) / 256);
    convert_kernel<<<cvt_blocks, 256>>>(face, fc, img, W1);
    gemm_pb_mma<<<dim3(HH / GN, (BB * SS) / GM), 256, DYN_SMEM>>>();
    pm_kernel<<<(BB * MM * HH) * 32 / 256, 256>>>(memory, label, W1, b1);
    e_kernel<<<dim3(SS / 8, BB), 256>>>(w2);
    softmax_kernel<<<BB, 1024>>>(fmask, alpha);
    context_kernel<<<BB, 512>>>(face, alpha, ctx);
}

// round 7
// speedup vs baseline: 2.8163x; 1.0093x over previous
#include <cuda_runtime.h>
#include <cuda_bf16.h>
#include <math_constants.h>
#include <cstdint>

// Problem constants
#define BB    32
#define SS    512
#define MM    8
#define HH    512
#define KBIG  1536          // face|fc|img (label folded into pm)
#define DIM1_ 2048
#define WCOLS 2560
#define EPSF  1e-5f

// GEMM tiling: CTA 128x256, warp tile 64x32, 16 warps (512 threads)
#define GM 128
#define GN 256
#define KC 64                        // bf16 k per chunk = 128 B/row
#define NCH (KBIG / KC)              // 24 chunks
#define A_TILE 16384                 // 128 rows x 128 B
#define B_TILE 32768                 // 256 rows x 128 B
#define STAGE_BYTES (2 * A_TILE + 2 * B_TILE)   // Ahi|Alo|Bhi|Blo = 96 KB
#define DYN_SMEM (2 * STAGE_BYTES + 1024)

// Scratch (device globals — no allocation allowed)
__device__ float g_pb[(size_t)BB * SS * HH];   // part_base [B*S, H]
__device__ float g_pm[BB * MM * HH];           // part_mem + label part + b1
__device__ float g_e [BB * MM * SS];           // logits e[b, m*S+s]
// Pre-converted bf16 hi/lo operands
__device__ __nv_bfloat16 g_Ahi[(size_t)BB * SS * KBIG];
__device__ __nv_bfloat16 g_Alo[(size_t)BB * SS * KBIG];
__device__ __nv_bfloat16 g_Whi[HH * KBIG];
__device__ __nv_bfloat16 g_Wlo[HH * KBIG];

__device__ __forceinline__ uint32_t smem_u32(const void* p) {
    return (uint32_t)__cvta_generic_to_shared(p);
}

#define LDMX4(r, addr) \
    asm volatile("ldmatrix.sync.aligned.m8n8.x4.shared.b16 {%0,%1,%2,%3}, [%4];" \
        : "=r"((r)[0]), "=r"((r)[1]), "=r"((r)[2]), "=r"((r)[3]) : "r"(addr))

#define MMA16816(d, a, b0v, b1v) \
    asm volatile("mma.sync.aligned.m16n8k16.row.col.f32.bf16.bf16.f32 " \
        "{%0,%1,%2,%3}, {%4,%5,%6,%7}, {%8,%9}, {%0,%1,%2,%3};" \
        : "+f"((d)[0]), "+f"((d)[1]), "+f"((d)[2]), "+f"((d)[3]) \
        : "r"((a)[0]), "r"((a)[1]), "r"((a)[2]), "r"((a)[3]), "r"(b0v), "r"(b1v))

#define CPASYNC(dst, src) \
    asm volatile("cp.async.cg.shared.global [%0], [%1], 16;" :: "r"(dst), "l"(src))
#define CPCOMMIT() asm volatile("cp.async.commit_group;" ::: "memory")
#define CPWAIT1()  asm volatile("cp.async.wait_group 1;" ::: "memory")

// 1-MUFU tanh (sm_75+ arch-agnostic PTX). Abs err ~5e-4 per element; after the
// w2-weighted 512-sum and softmax this lands ~1e-4 relative — 10x margin.
__device__ __forceinline__ float fast_tanh(float x) {
    float y;
    asm("tanh.approx.f32 %0, %1;" : "=f"(y) : "f"(x));
    return y;
}

// ---------------------------------------------------------------------------
// Kernel 0: one-shot fp32 -> bf16 hi/lo conversion of features and W1 slice.
// ---------------------------------------------------------------------------
#define FEAT4 ((size_t)BB * SS * KBIG / 4)   // 6291456
#define W4    (HH * KBIG / 4)                // 196608

__device__ __forceinline__ void cvt4(float4 v, uint2& hi, uint2& lo) {
    __nv_bfloat162 h0, h1, l0, l1;
    h0.x = __float2bfloat16_rn(v.x); h0.y = __float2bfloat16_rn(v.y);
    h1.x = __float2bfloat16_rn(v.z); h1.y = __float2bfloat16_rn(v.w);
    l0.x = __float2bfloat16_rn(v.x - __bfloat162float(h0.x));
    l0.y = __float2bfloat16_rn(v.y - __bfloat162float(h0.y));
    l1.x = __float2bfloat16_rn(v.z - __bfloat162float(h1.x));
    l1.y = __float2bfloat16_rn(v.w - __bfloat162float(h1.y));
    hi = make_uint2(*(uint32_t*)&h0, *(uint32_t*)&h1);
    lo = make_uint2(*(uint32_t*)&l0, *(uint32_t*)&l1);
}

__global__ __launch_bounds__(256)
void convert_kernel(const float* __restrict__ face, const float* __restrict__ fc,
                    const float* __restrict__ img,  const float* __restrict__ W1)
{
    size_t idx = (size_t)blockIdx.x * 256 + threadIdx.x;
    if (idx < FEAT4) {
        const size_t r  = idx / (KBIG / 4);
        const int    k  = (int)(idx % (KBIG / 4)) * 4;
        const int    f  = k >> 9;
        const float* src = ((f == 0) ? face : (f == 1 ? fc : img)) + r * 512 + (k & 511);
        uint2 hi, lo;
        cvt4(*(const float4*)src, hi, lo);
        *(uint2*)&g_Ahi[r * KBIG + k] = hi;
        *(uint2*)&g_Alo[r * KBIG + k] = lo;
    } else {
        idx -= FEAT4;
        if (idx >= W4) return;
        const int h = (int)(idx / (KBIG / 4));
        const int k = (int)(idx % (KBIG / 4)) * 4;
        uint2 hi, lo;
        cvt4(*(const float4*)&W1[(size_t)h * WCOLS + k], hi, lo);
        *(uint2*)&g_Whi[h * KBIG + k] = hi;
        *(uint2*)&g_Wlo[h * KBIG + k] = lo;
    }
}

// ---------------------------------------------------------------------------
// GEMM helpers (stage layout: Ahi 0 | Alo 16K | Bhi 32K | Blo 64K)
// 512 threads per CTA.
// ---------------------------------------------------------------------------
__device__ __forceinline__ void load_stage(uint32_t sb, int tid,
                                           int rowBase, int colBase, int kt)
{
#pragma unroll
    for (int i = 0; i < 2; i++) {              // A: 128 rows x 8 slots / 512
        const int v   = tid + i * 512;
        const int row = v >> 3;
        const int cs  = v & 7;
        const uint32_t off = (uint32_t)row * 128 + cs * 16;
        const uint32_t sw  = off ^ ((off >> 3) & 0x70);
        const size_t aoff = (size_t)(rowBase + row) * KBIG + kt * KC + cs * 8;
        CPASYNC(sb + sw,          (const char*)&g_Ahi[aoff]);
        CPASYNC(sb + A_TILE + sw, (const char*)&g_Alo[aoff]);
    }
#pragma unroll
    for (int i = 0; i < 4; i++) {              // B: 256 rows x 8 slots / 512
        const int v   = tid + i * 512;
        const int row = v >> 3;
        const int cs  = v & 7;
        const uint32_t off = (uint32_t)row * 128 + cs * 16;
        const uint32_t sw  = off ^ ((off >> 3) & 0x70);
        const size_t boff = (size_t)(colBase + row) * KBIG + kt * KC + cs * 8;
        CPASYNC(sb + 2 * A_TILE + sw,          (const char*)&g_Whi[boff]);
        CPASYNC(sb + 2 * A_TILE + B_TILE + sw, (const char*)&g_Wlo[boff]);
    }
}

__device__ __forceinline__ void mma_stage(uint32_t sb, float (&d)[4][4][4],
        int mw, int nw, int a_r, int a_kh, int b_r, int b_kh)
{
#pragma unroll
    for (int ks = 0; ks < 4; ks++) {
        const uint32_t kb = (uint32_t)(ks * 2) * 16;

        uint32_t ah[4][4];
#pragma unroll
        for (int i = 0; i < 4; i++) {
            const uint32_t off = (uint32_t)(mw * 64 + i * 16 + a_r) * 128 + kb + a_kh * 16;
            LDMX4(ah[i], sb + (off ^ ((off >> 3) & 0x70)));
        }
        uint32_t bh[2][4];
#pragma unroll
        for (int p = 0; p < 2; p++) {
            const uint32_t off = (uint32_t)(nw * 32 + p * 16 + b_r) * 128 + kb + b_kh * 16;
            LDMX4(bh[p], sb + 2 * A_TILE + (off ^ ((off >> 3) & 0x70)));
        }
        // hi * hi
#pragma unroll
        for (int i = 0; i < 4; i++)
#pragma unroll
            for (int p = 0; p < 2; p++) {
                MMA16816(d[i][2 * p],     ah[i], bh[p][0], bh[p][1]);
                MMA16816(d[i][2 * p + 1], ah[i], bh[p][2], bh[p][3]);
            }
        // hi * lo
        {
            uint32_t bl[2][4];
#pragma unroll
            for (int p = 0; p < 2; p++) {
                const uint32_t off = (uint32_t)(nw * 32 + p * 16 + b_r) * 128 + kb + b_kh * 16;
                LDMX4(bl[p], sb + 2 * A_TILE + B_TILE + (off ^ ((off >> 3) & 0x70)));
            }
#pragma unroll
            for (int i = 0; i < 4; i++)
#pragma unroll
                for (int p = 0; p < 2; p++) {
                    MMA16816(d[i][2 * p],     ah[i], bl[p][0], bl[p][1]);
                    MMA16816(d[i][2 * p + 1], ah[i], bl[p][2], bl[p][3]);
                }
        }
        // lo * hi
        {
            uint32_t al[4][4];
#pragma unroll
            for (int i = 0; i < 4; i++) {
                const uint32_t off = (uint32_t)(mw * 64 + i * 16 + a_r) * 128 + kb + a_kh * 16;
                LDMX4(al[i], sb + A_TILE + (off ^ ((off >> 3) & 0x70)));
            }
#pragma unroll
            for (int i = 0; i < 4; i++)
#pragma unroll
                for (int p = 0; p < 2; p++) {
                    MMA16816(d[i][2 * p],     al[i], bh[p][0], bh[p][1]);
                    MMA16816(d[i][2 * p + 1], al[i], bh[p][2], bh[p][3]);
                }
        }
    }
}

// ---------------------------------------------------------------------------
// Kernel 1: part_base via bf16 mma.sync, cp.async 2-stage pipeline.
// Grid (2, 128), 512 threads; 16 warps of 64x32 (4 warps/SMSP).
// ---------------------------------------------------------------------------
__global__ __launch_bounds__(512, 1)
void gemm_pb_mma(void)
{
    extern __shared__ char dynsmem[];
    const uint32_t dynaddr = smem_u32(dynsmem);
    const uint32_t sbase = (dynaddr + 1023) & ~1023u;

    const int tid  = threadIdx.x;
    const int warp = tid >> 5;
    const int lane = tid & 31;
    const int mw = warp >> 3;            // 0..1 : m offset mw*64
    const int nw = warp & 7;             // 0..7 : n offset nw*32
    const int colBase = blockIdx.x * GN;
    const int rowBase = blockIdx.y * GM;

    const int a_r  = lane & 15;
    const int a_kh = lane >> 4;
    const int b_r  = (lane & 7) + ((lane >> 4) << 3);
    const int b_kh = (lane >> 3) & 1;

    float d[4][4][4];
#pragma unroll
    for (int i = 0; i < 4; i++)
#pragma unroll
        for (int j = 0; j < 4; j++)
#pragma unroll
            for (int q = 0; q < 4; q++) d[i][j][q] = 0.f;

    load_stage(sbase, tid, rowBase, colBase, 0);
    CPCOMMIT();
    load_stage(sbase + STAGE_BYTES, tid, rowBase, colBase, 1);
    CPCOMMIT();

    for (int kt = 0; kt < NCH; kt++) {
        CPWAIT1();
        __syncthreads();
        mma_stage(sbase + (kt & 1) * STAGE_BYTES, d, mw, nw, a_r, a_kh, b_r, b_kh);
        __syncthreads();
        if (kt + 2 < NCH)
            load_stage(sbase + (kt & 1) * STAGE_BYTES, tid, rowBase, colBase, kt + 2);
        CPCOMMIT();
    }

    // Epilogue: fragment layout -> g_pb
    const int r0 = rowBase + mw * 64 + (lane >> 2);
    const int c0 = colBase + nw * 32 + (lane & 3) * 2;
#pragma unroll
    for (int i = 0; i < 4; i++)
#pragma unroll
        for (int nt = 0; nt < 4; nt++) {
            const int row = r0 + i * 16;
            const int col = c0 + nt * 8;
            *(float2*)&g_pb[(size_t)row * HH + col]       = make_float2(d[i][nt][0], d[i][nt][1]);
            *(float2*)&g_pb[(size_t)(row + 8) * HH + col] = make_float2(d[i][nt][2], d[i][nt][3]);
        }
}

// ---------------------------------------------------------------------------
// Kernel 2: pm[b,m,h] = memory[b,m,:]·W1[h,2048:] + label[b,:]·W1[h,1536:2048] + b1[h]
// ---------------------------------------------------------------------------
__global__ __launch_bounds__(256)
void pm_kernel(const float* __restrict__ memory, const float* __restrict__ label,
               const float* __restrict__ W1, const float* __restrict__ b1)
{
    const int gw   = (blockIdx.x * blockDim.x + threadIdx.x) >> 5;
    const int lane = threadIdx.x & 31;
    const int h  = gw & (HH - 1);
    const int bm = gw >> 9;
    const int b  = bm >> 3;

    const float* __restrict__ wmem = W1 + (size_t)h * WCOLS + DIM1_;
    const float* __restrict__ wlab = W1 + (size_t)h * WCOLS + KBIG;
    const float* __restrict__ mrow = memory + (size_t)bm * HH;
    const float* __restrict__ lrow = label  + (size_t)b * 512;

    float acc = 0.f;
#pragma unroll 4
    for (int d = lane; d < HH; d += 32)
        acc = fmaf(wmem[d], mrow[d], fmaf(wlab[d], lrow[d], acc));
#pragma unroll
    for (int o = 16; o; o >>= 1) acc += __shfl_xor_sync(0xFFFFFFFFu, acc, o);
    if (lane == 0) g_pm[gw] = acc + b1[h];
}

// ---------------------------------------------------------------------------
// Kernel 3: e[b, m*S+s] = sum_h w2[h] * tanh(pb[b,s,h] + pm[b,m,h])
// ---------------------------------------------------------------------------
__global__ __launch_bounds__(256)
void e_kernel(const float* __restrict__ w2)
{
    __shared__ float pm_s[MM][HH];
    __shared__ float w2_s[HH];

    const int b   = blockIdx.y;
    const int tid = threadIdx.x;
    for (int i = tid; i < MM * HH; i += 256) ((float*)pm_s)[i] = g_pm[b * MM * HH + i];
    for (int i = tid; i < HH; i += 256)      w2_s[i] = w2[i];
    __syncthreads();

    const int warp = tid >> 5, lane = tid & 31;
    const int s = blockIdx.x * 8 + warp;
    const float* __restrict__ pb = g_pb + (size_t)(b * SS + s) * HH;

    float acc[MM];
#pragma unroll
    for (int m = 0; m < MM; m++) acc[m] = 0.f;

    for (int h = lane; h < HH; h += 32) {
        const float pbv = pb[h];
        const float w2v = w2_s[h];
#pragma unroll
        for (int m = 0; m < MM; m++)
            acc[m] = fmaf(w2v, fast_tanh(pbv + pm_s[m][h]), acc[m]);
    }
#pragma unroll
    for (int m = 0; m < MM; m++)
#pragma unroll
        for (int o = 16; o; o >>= 1) acc[m] += __shfl_xor_sync(0xFFFFFFFFu, acc[m], o);

    if (lane == 0) {
#pragma unroll
        for (int m = 0; m < MM; m++) g_e[b * MM * SS + m * SS + s] = acc[m];
    }
}

// ---------------------------------------------------------------------------
// Kernel 4: softmax over 4096, *mask, renorm by (masked_sum + EPS).
// ---------------------------------------------------------------------------
__global__ __launch_bounds__(1024)
void softmax_kernel(const float* __restrict__ face_mask, float* __restrict__ alpha)
{
    __shared__ float sred[32];
    const int b = blockIdx.x;
    const int tid = threadIdx.x;
    const int w = tid >> 5, l = tid & 31;
    const float* __restrict__ e = g_e + b * (MM * SS);

    float v[4];
    float mx = -CUDART_INF_F;
#pragma unroll
    for (int i = 0; i < 4; i++) { v[i] = e[tid + i * 1024]; mx = fmaxf(mx, v[i]); }

#pragma unroll
    for (int o = 16; o; o >>= 1) mx = fmaxf(mx, __shfl_xor_sync(0xFFFFFFFFu, mx, o));
    if (l == 0) sred[w] = mx;
    __syncthreads();
    if (tid < 32) {
        float t = sred[tid];
#pragma unroll
        for (int o = 16; o; o >>= 1) t = fmaxf(t, __shfl_xor_sync(0xFFFFFFFFu, t, o));
        if (tid == 0) sred[0] = t;
    }
    __syncthreads();
    mx = sred[0];
    __syncthreads();

    float sum = 0.f;
#pragma unroll
    for (int i = 0; i < 4; i++) { v[i] = __expf(v[i] - mx); sum += v[i]; }
#pragma unroll
    for (int o = 16; o; o >>= 1) sum += __shfl_xor_sync(0xFFFFFFFFu, sum, o);
    if (l == 0) sred[w] = sum;
    __syncthreads();
    if (tid < 32) {
        float t = sred[tid];
#pragma unroll
        for (int o = 16; o; o >>= 1) t += __shfl_xor_sync(0xFFFFFFFFu, t, o);
        if (tid == 0) sred[0] = t;
    }
    __syncthreads();
    const float Z = sred[0];
    __syncthreads();

    const float invZ = 1.f / Z;
    float msum = 0.f;
#pragma unroll
    for (int i = 0; i < 4; i++) {
        const int idx = tid + i * 1024;
        const float mk = face_mask[b * SS + (idx & 511)];
        v[i] = v[i] * invZ * mk;
        msum += v[i];
    }
#pragma unroll
    for (int o = 16; o; o >>= 1) msum += __shfl_xor_sync(0xFFFFFFFFu, msum, o);
    if (l == 0) sred[w] = msum;
    __syncthreads();
    if (tid < 32) {
        float t = sred[tid];
#pragma unroll
        for (int o = 16; o; o >>= 1) t += __shfl_xor_sync(0xFFFFFFFFu, t, o);
        if (tid == 0) sred[0] = t;
    }
    __syncthreads();
    const float inv = 1.f / (sred[0] + EPSF);

#pragma unroll
    for (int i = 0; i < 4; i++)
        alpha[b * (MM * SS) + tid + i * 1024] = v[i] * inv;
}

// ---------------------------------------------------------------------------
// Kernel 5: context[b,d] = sum_s (sum_m alpha[b,m,s]) * face[b,s,d]
// ---------------------------------------------------------------------------
__global__ __launch_bounds__(512)
void context_kernel(const float* __restrict__ face, const float* __restrict__ alpha,
                    float* __restrict__ ctx)
{
    __shared__ float asum[SS];
    const int b = blockIdx.x;
    const int tid = threadIdx.x;

    float a = 0.f;
#pragma unroll
    for (int m = 0; m < MM; m++) a += alpha[b * (MM * SS) + m * SS + tid];
    asum[tid] = a;
    __syncthreads();

    const float* __restrict__ fb = face + (size_t)b * SS * 512;
    float c0 = 0.f, c1 = 0.f, c2 = 0.f, c3 = 0.f;
    for (int s = 0; s < SS; s += 4) {
        c0 = fmaf(asum[s + 0], fb[(size_t)(s + 0) * 512 + tid], c0);
        c1 = fmaf(asum[s + 1], fb[(size_t)(s + 1) * 512 + tid], c1);
        c2 = fmaf(asum[s + 2], fb[(size_t)(s + 2) * 512 + tid], c2);
        c3 = fmaf(asum[s + 3], fb[(size_t)(s + 3) * 512 + tid], c3);
    }
    ctx[b * 512 + tid] = (c0 + c1) + (c2 + c3);
}

// ---------------------------------------------------------------------------
// Launch. Inputs: 0 fc, 1 img, 2 label, 3 memory, 4 face, 5 face_mask,
// 6 W1, 7 b1, 8 w2.  Output: alpha [B, M*S] then context [B, DF].
// ---------------------------------------------------------------------------
extern "C" void kernel_launch(void* const* d_in, const int* in_sizes, int n_in,
                              void* d_out, int out_size)
{
    const float* fc     = (const float*)d_in[0];
    const float* img    = (const float*)d_in[1];
    const float* label  = (const float*)d_in[2];
    const float* memory = (const float*)d_in[3];
    const float* face   = (const float*)d_in[4];
    const float* fmask  = (const float*)d_in[5];
    const float* W1     = (const float*)d_in[6];
    const float* b1     = (const float*)d_in[7];
    const float* w2     = (const float*)d_in[8];

    float* out   = (float*)d_out;
    float* alpha = out;                      // [B, M*S]
    float* ctx   = out + BB * MM * SS;       // [B, DF]

    cudaFuncSetAttribute(gemm_pb_mma, cudaFuncAttributeMaxDynamicSharedMemorySize, DYN_SMEM);

    const int cvt_blocks = (int)((FEAT4 + W4 + 255) / 256);
    convert_kernel<<<cvt_blocks, 256>>>(face, fc, img, W1);
    gemm_pb_mma<<<dim3(HH / GN, (BB * SS) / GM), 512, DYN_SMEM>>>();
    pm_kernel<<<(BB * MM * HH) * 32 / 256, 256>>>(memory, label, W1, b1);
    e_kernel<<<dim3(SS / 8, BB), 256>>>(w2);
    softmax_kernel<<<BB, 1024>>>(fmask, alpha);
    context_kernel<<<BB, 512>>>(face, alpha, ctx);
}

// round 8
// speedup vs baseline: 2.8518x; 1.0126x over previous
#include <cuda_runtime.h>
#include <cuda_bf16.h>
#include <math_constants.h>
#include <cstdint>

// Problem constants
#define BB    32
#define SS    512
#define MM    8
#define HH    512
#define KBIG  1536          // face|fc|img (label folded into pm)
#define DIM1_ 2048
#define WCOLS 2560
#define EPSF  1e-5f

// GEMM tiling: CTA 128x256, warp tile 64x32, 16 warps (512 threads)
#define GM 128
#define GN 256
#define KC 64                        // bf16 k per chunk = 128 B/row
#define NCH (KBIG / KC)              // 24 chunks
#define A_TILE 16384                 // 128 rows x 128 B
#define B_TILE 32768                 // 256 rows x 128 B
#define STAGE_BYTES (2 * A_TILE + 2 * B_TILE)   // Ahi|Alo|Bhi|Blo = 96 KB
#define DYN_SMEM (2 * STAGE_BYTES + 1024)

// Scratch (device globals — no allocation allowed)
__device__ float g_pb[(size_t)BB * SS * HH];   // part_base [B*S, H]
__device__ float g_pm[BB * MM * HH];           // part_mem + label part + b1
__device__ float g_e [BB * MM * SS];           // logits e[b, m*S+s]
// Pre-converted bf16 hi/lo W1 slice (W converted once; A converted in-GEMM)
__device__ __nv_bfloat16 g_Whi[HH * KBIG];
__device__ __nv_bfloat16 g_Wlo[HH * KBIG];

__device__ __forceinline__ uint32_t smem_u32(const void* p) {
    return (uint32_t)__cvta_generic_to_shared(p);
}

#define LDMX4(r, addr) \
    asm volatile("ldmatrix.sync.aligned.m8n8.x4.shared.b16 {%0,%1,%2,%3}, [%4];" \
        : "=r"((r)[0]), "=r"((r)[1]), "=r"((r)[2]), "=r"((r)[3]) : "r"(addr))

#define MMA16816(d, a, b0v, b1v) \
    asm volatile("mma.sync.aligned.m16n8k16.row.col.f32.bf16.bf16.f32 " \
        "{%0,%1,%2,%3}, {%4,%5,%6,%7}, {%8,%9}, {%0,%1,%2,%3};" \
        : "+f"((d)[0]), "+f"((d)[1]), "+f"((d)[2]), "+f"((d)[3]) \
        : "r"((a)[0]), "r"((a)[1]), "r"((a)[2]), "r"((a)[3]), "r"(b0v), "r"(b1v))

#define CPASYNC(dst, src) \
    asm volatile("cp.async.cg.shared.global [%0], [%1], 16;" :: "r"(dst), "l"(src))
#define CPCOMMIT() asm volatile("cp.async.commit_group;" ::: "memory")
#define CPWAIT1()  asm volatile("cp.async.wait_group 1;" ::: "memory")

// 1-MUFU tanh (arch-agnostic PTX, sm_75+)
__device__ __forceinline__ float fast_tanh(float x) {
    float y;
    asm("tanh.approx.f32 %0, %1;" : "=f"(y) : "f"(x));
    return y;
}

// fp32x4 -> bf16 hi/lo pairs
__device__ __forceinline__ void cvt4(float4 v, uint2& hi, uint2& lo) {
    __nv_bfloat162 h0, h1, l0, l1;
    h0.x = __float2bfloat16_rn(v.x); h0.y = __float2bfloat16_rn(v.y);
    h1.x = __float2bfloat16_rn(v.z); h1.y = __float2bfloat16_rn(v.w);
    l0.x = __float2bfloat16_rn(v.x - __bfloat162float(h0.x));
    l0.y = __float2bfloat16_rn(v.y - __bfloat162float(h0.y));
    l1.x = __float2bfloat16_rn(v.z - __bfloat162float(h1.x));
    l1.y = __float2bfloat16_rn(v.w - __bfloat162float(h1.y));
    hi = make_uint2(*(uint32_t*)&h0, *(uint32_t*)&h1);
    lo = make_uint2(*(uint32_t*)&l0, *(uint32_t*)&l1);
}

// ---------------------------------------------------------------------------
// Kernel 0: one-shot fp32 -> bf16 hi/lo conversion of the W1 slice only.
// ---------------------------------------------------------------------------
#define W4 (HH * KBIG / 4)                   // 196608 float4s

__global__ __launch_bounds__(256)
void convert_w_kernel(const float* __restrict__ W1)
{
    const int idx = blockIdx.x * 256 + threadIdx.x;
    if (idx >= W4) return;
    const int h = idx / (KBIG / 4);
    const int k = (idx % (KBIG / 4)) * 4;
    uint2 hi, lo;
    cvt4(*(const float4*)&W1[(size_t)h * WCOLS + k], hi, lo);
    *(uint2*)&g_Whi[h * KBIG + k] = hi;
    *(uint2*)&g_Wlo[h * KBIG + k] = lo;
}

// ---------------------------------------------------------------------------
// GEMM (stage layout: Ahi 0 | Alo 16K | Bhi 32K | Blo 64K), 512 threads.
// A converted in-kernel inside the HMMA shadow; B (W1 hi/lo) via cp.async.
// ---------------------------------------------------------------------------
__device__ __forceinline__ void load_B(uint32_t sb, int tid, int colBase, int kt)
{
#pragma unroll
    for (int i = 0; i < 4; i++) {              // 256 rows x 8 slots / 512 thr
        const int v   = tid + i * 512;
        const int row = v >> 3;
        const int cs  = v & 7;
        const uint32_t off = (uint32_t)row * 128 + cs * 16;
        const uint32_t sw  = off ^ ((off >> 3) & 0x70);
        const size_t boff = (size_t)(colBase + row) * KBIG + kt * KC + cs * 8;
        CPASYNC(sb + 2 * A_TILE + sw,          (const char*)&g_Whi[boff]);
        CPASYNC(sb + 2 * A_TILE + B_TILE + sw, (const char*)&g_Wlo[boff]);
    }
}

// Load one A chunk (fp32) into registers: thread handles row tid>>2, 16 cols.
__device__ __forceinline__ void load_A(float4 (&av)[4], int tid, int rowBase, int kt,
        const float* __restrict__ face, const float* __restrict__ fc,
        const float* __restrict__ img)
{
    const int f = kt >> 3;
    const float* src = (f == 0) ? face : (f == 1 ? fc : img);
    const int row = rowBase + (tid >> 2);
    const int col = (kt & 7) * KC + (tid & 3) * 16;
    const float* p = &src[(size_t)row * 512 + col];
#pragma unroll
    for (int j = 0; j < 4; j++) av[j] = *(const float4*)(p + j * 4);
}

// Convert registers -> bf16 hi/lo, store swizzled into stage.
__device__ __forceinline__ void sts_A(uint32_t sb, int tid, const float4 (&av)[4])
{
    const uint32_t rowoff = (uint32_t)(tid >> 2) * 128 + (tid & 3) * 32;
#pragma unroll
    for (int j = 0; j < 4; j++) {
        uint2 hi, lo;
        cvt4(av[j], hi, lo);
        const uint32_t off = rowoff + j * 8;
        const uint32_t sw  = off ^ ((off >> 3) & 0x70);
        *(uint2*)(uintptr_t)__cvta_shared_to_generic(sb + sw)          = hi;
        *(uint2*)(uintptr_t)__cvta_shared_to_generic(sb + A_TILE + sw) = lo;
    }
}

__device__ __forceinline__ void mma_stage(uint32_t sb, float (&d)[4][4][4],
        int mw, int nw, int a_r, int a_kh, int b_r, int b_kh)
{
#pragma unroll
    for (int ks = 0; ks < 4; ks++) {
        const uint32_t kb = (uint32_t)(ks * 2) * 16;

        uint32_t ah[4][4];
#pragma unroll
        for (int i = 0; i < 4; i++) {
            const uint32_t off = (uint32_t)(mw * 64 + i * 16 + a_r) * 128 + kb + a_kh * 16;
            LDMX4(ah[i], sb + (off ^ ((off >> 3) & 0x70)));
        }
        uint32_t bh[2][4];
#pragma unroll
        for (int p = 0; p < 2; p++) {
            const uint32_t off = (uint32_t)(nw * 32 + p * 16 + b_r) * 128 + kb + b_kh * 16;
            LDMX4(bh[p], sb + 2 * A_TILE + (off ^ ((off >> 3) & 0x70)));
        }
        // hi * hi
#pragma unroll
        for (int i = 0; i < 4; i++)
#pragma unroll
            for (int p = 0; p < 2; p++) {
                MMA16816(d[i][2 * p],     ah[i], bh[p][0], bh[p][1]);
                MMA16816(d[i][2 * p + 1], ah[i], bh[p][2], bh[p][3]);
            }
        // hi * lo
        {
            uint32_t bl[2][4];
#pragma unroll
            for (int p = 0; p < 2; p++) {
                const uint32_t off = (uint32_t)(nw * 32 + p * 16 + b_r) * 128 + kb + b_kh * 16;
                LDMX4(bl[p], sb + 2 * A_TILE + B_TILE + (off ^ ((off >> 3) & 0x70)));
            }
#pragma unroll
            for (int i = 0; i < 4; i++)
#pragma unroll
                for (int p = 0; p < 2; p++) {
                    MMA16816(d[i][2 * p],     ah[i], bl[p][0], bl[p][1]);
                    MMA16816(d[i][2 * p + 1], ah[i], bl[p][2], bl[p][3]);
                }
        }
        // lo * hi
        {
            uint32_t al[4][4];
#pragma unroll
            for (int i = 0; i < 4; i++) {
                const uint32_t off = (uint32_t)(mw * 64 + i * 16 + a_r) * 128 + kb + a_kh * 16;
                LDMX4(al[i], sb + A_TILE + (off ^ ((off >> 3) & 0x70)));
            }
#pragma unroll
            for (int i = 0; i < 4; i++)
#pragma unroll
                for (int p = 0; p < 2; p++) {
                    MMA16816(d[i][2 * p],     al[i], bh[p][0], bh[p][1]);
                    MMA16816(d[i][2 * p + 1], al[i], bh[p][2], bh[p][3]);
                }
        }
    }
}

__global__ __launch_bounds__(512, 1)
void gemm_pb_mma(const float* __restrict__ face, const float* __restrict__ fc,
                 const float* __restrict__ img)
{
    extern __shared__ char dynsmem[];
    const uint32_t dynaddr = smem_u32(dynsmem);
    const uint32_t sbase = (dynaddr + 1023) & ~1023u;

    const int tid  = threadIdx.x;
    const int warp = tid >> 5;
    const int lane = tid & 31;
    const int mw = warp >> 3;            // 0..1 : m offset mw*64
    const int nw = warp & 7;             // 0..7 : n offset nw*32
    const int colBase = blockIdx.x * GN;
    const int rowBase = blockIdx.y * GM;

    const int a_r  = lane & 15;
    const int a_kh = lane >> 4;
    const int b_r  = (lane & 7) + ((lane >> 4) << 3);
    const int b_kh = (lane >> 3) & 1;

    float d[4][4][4];
#pragma unroll
    for (int i = 0; i < 4; i++)
#pragma unroll
        for (int j = 0; j < 4; j++)
#pragma unroll
            for (int q = 0; q < 4; q++) d[i][j][q] = 0.f;

    float4 av[4];

    // Prologue: B0, B1 in flight; A0 converted into stage0; A1 in regs.
    load_A(av, tid, rowBase, 0, face, fc, img);
    load_B(sbase, tid, colBase, 0);
    CPCOMMIT();
    load_B(sbase + STAGE_BYTES, tid, colBase, 1);
    CPCOMMIT();
    sts_A(sbase, tid, av);
    load_A(av, tid, rowBase, 1, face, fc, img);

    for (int kt = 0; kt < NCH; kt++) {
        CPWAIT1();                         // B(kt) arrived
        __syncthreads();
        // In the HMMA shadow: stage next A (disjoint buffer), prefetch A after.
        if (kt + 1 < NCH) sts_A(sbase + ((kt + 1) & 1) * STAGE_BYTES, tid, av);
        if (kt + 2 < NCH) load_A(av, tid, rowBase, kt + 2, face, fc, img);
        mma_stage(sbase + (kt & 1) * STAGE_BYTES, d, mw, nw, a_r, a_kh, b_r, b_kh);
        __syncthreads();
        if (kt + 2 < NCH) load_B(sbase + (kt & 1) * STAGE_BYTES, tid, colBase, kt + 2);
        CPCOMMIT();                        // keep group count uniform
    }

    // Epilogue: fragment layout -> g_pb
    const int r0 = rowBase + mw * 64 + (lane >> 2);
    const int c0 = colBase + nw * 32 + (lane & 3) * 2;
#pragma unroll
    for (int i = 0; i < 4; i++)
#pragma unroll
        for (int nt = 0; nt < 4; nt++) {
            const int row = r0 + i * 16;
            const int col = c0 + nt * 8;
            *(float2*)&g_pb[(size_t)row * HH + col]       = make_float2(d[i][nt][0], d[i][nt][1]);
            *(float2*)&g_pb[(size_t)(row + 8) * HH + col] = make_float2(d[i][nt][2], d[i][nt][3]);
        }
}

// ---------------------------------------------------------------------------
// Kernel 2: pm[b,m,h] = memory[b,m,:]·W1[h,2048:] + label[b,:]·W1[h,1536:2048] + b1[h]
// ---------------------------------------------------------------------------
__global__ __launch_bounds__(256)
void pm_kernel(const float* __restrict__ memory, const float* __restrict__ label,
               const float* __restrict__ W1, const float* __restrict__ b1)
{
    const int gw   = (blockIdx.x * blockDim.x + threadIdx.x) >> 5;
    const int lane = threadIdx.x & 31;
    const int h  = gw & (HH - 1);
    const int bm = gw >> 9;
    const int b  = bm >> 3;

    const float* __restrict__ wmem = W1 + (size_t)h * WCOLS + DIM1_;
    const float* __restrict__ wlab = W1 + (size_t)h * WCOLS + KBIG;
    const float* __restrict__ mrow = memory + (size_t)bm * HH;
    const float* __restrict__ lrow = label  + (size_t)b * 512;

    float acc = 0.f;
#pragma unroll 4
    for (int d = lane; d < HH; d += 32)
        acc = fmaf(wmem[d], mrow[d], fmaf(wlab[d], lrow[d], acc));
#pragma unroll
    for (int o = 16; o; o >>= 1) acc += __shfl_xor_sync(0xFFFFFFFFu, acc, o);
    if (lane == 0) g_pm[gw] = acc + b1[h];
}

// ---------------------------------------------------------------------------
// Kernel 3: e[b, m*S+s] = sum_h w2[h] * tanh(pb[b,s,h] + pm[b,m,h]) — float4.
// ---------------------------------------------------------------------------
__global__ __launch_bounds__(256)
void e_kernel(const float* __restrict__ w2)
{
    __shared__ float pm_s[MM][HH];
    __shared__ float w2_s[HH];

    const int b   = blockIdx.y;
    const int tid = threadIdx.x;
    for (int i = tid; i < MM * HH; i += 256) ((float*)pm_s)[i] = g_pm[b * MM * HH + i];
    for (int i = tid; i < HH; i += 256)      w2_s[i] = w2[i];
    __syncthreads();

    const int warp = tid >> 5, lane = tid & 31;
    const int s = blockIdx.x * 8 + warp;
    const float4* __restrict__ pb4 = (const float4*)(g_pb + (size_t)(b * SS + s) * HH);
    const float4* __restrict__ w4  = (const float4*)w2_s;

    float acc[MM];
#pragma unroll
    for (int m = 0; m < MM; m++) acc[m] = 0.f;

#pragma unroll
    for (int i = 0; i < 4; i++) {
        const int hv = lane + i * 32;             // float4 index: h = hv*4
        const float4 p = pb4[hv];
        const float4 w = w4[hv];
#pragma unroll
        for (int m = 0; m < MM; m++) {
            const float4 q = ((const float4*)pm_s[m])[hv];
            float t;
            t = fast_tanh(p.x + q.x); acc[m] = fmaf(w.x, t, acc[m]);
            t = fast_tanh(p.y + q.y); acc[m] = fmaf(w.y, t, acc[m]);
            t = fast_tanh(p.z + q.z); acc[m] = fmaf(w.z, t, acc[m]);
            t = fast_tanh(p.w + q.w); acc[m] = fmaf(w.w, t, acc[m]);
        }
    }
#pragma unroll
    for (int m = 0; m < MM; m++)
#pragma unroll
        for (int o = 16; o; o >>= 1) acc[m] += __shfl_xor_sync(0xFFFFFFFFu, acc[m], o);

    if (lane == 0) {
#pragma unroll
        for (int m = 0; m < MM; m++) g_e[b * MM * SS + m * SS + s] = acc[m];
    }
}

// ---------------------------------------------------------------------------
// Kernel 4: softmax over 4096, *mask, renorm by (masked_sum + EPS).
// ---------------------------------------------------------------------------
__global__ __launch_bounds__(1024)
void softmax_kernel(const float* __restrict__ face_mask, float* __restrict__ alpha)
{
    __shared__ float sred[32];
    const int b = blockIdx.x;
    const int tid = threadIdx.x;
    const int w = tid >> 5, l = tid & 31;
    const float* __restrict__ e = g_e + b * (MM * SS);

    float v[4];
    float mx = -CUDART_INF_F;
#pragma unroll
    for (int i = 0; i < 4; i++) { v[i] = e[tid + i * 1024]; mx = fmaxf(mx, v[i]); }

#pragma unroll
    for (int o = 16; o; o >>= 1) mx = fmaxf(mx, __shfl_xor_sync(0xFFFFFFFFu, mx, o));
    if (l == 0) sred[w] = mx;
    __syncthreads();
    if (tid < 32) {
        float t = sred[tid];
#pragma unroll
        for (int o = 16; o; o >>= 1) t = fmaxf(t, __shfl_xor_sync(0xFFFFFFFFu, t, o));
        if (tid == 0) sred[0] = t;
    }
    __syncthreads();
    mx = sred[0];
    __syncthreads();

    float sum = 0.f;
#pragma unroll
    for (int i = 0; i < 4; i++) { v[i] = __expf(v[i] - mx); sum += v[i]; }
#pragma unroll
    for (int o = 16; o; o >>= 1) sum += __shfl_xor_sync(0xFFFFFFFFu, sum, o);
    if (l == 0) sred[w] = sum;
    __syncthreads();
    if (tid < 32) {
        float t = sred[tid];
#pragma unroll
        for (int o = 16; o; o >>= 1) t += __shfl_xor_sync(0xFFFFFFFFu, t, o);
        if (tid == 0) sred[0] = t;
    }
    __syncthreads();
    const float Z = sred[0];
    __syncthreads();

    const float invZ = 1.f / Z;
    float msum = 0.f;
#pragma unroll
    for (int i = 0; i < 4; i++) {
        const int idx = tid + i * 1024;
        const float mk = face_mask[b * SS + (idx & 511)];
        v[i] = v[i] * invZ * mk;
        msum += v[i];
    }
#pragma unroll
    for (int o = 16; o; o >>= 1) msum += __shfl_xor_sync(0xFFFFFFFFu, msum, o);
    if (l == 0) sred[w] = msum;
    __syncthreads();
    if (tid < 32) {
        float t = sred[tid];
#pragma unroll
        for (int o = 16; o; o >>= 1) t += __shfl_xor_sync(0xFFFFFFFFu, t, o);
        if (tid == 0) sred[0] = t;
    }
    __syncthreads();
    const float inv = 1.f / (sred[0] + EPSF);

#pragma unroll
    for (int i = 0; i < 4; i++)
        alpha[b * (MM * SS) + tid + i * 1024] = v[i] * inv;
}

// ---------------------------------------------------------------------------
// Kernel 5: context[b,d] = sum_s (sum_m alpha[b,m,s]) * face[b,s,d]
// ---------------------------------------------------------------------------
__global__ __launch_bounds__(512)
void context_kernel(const float* __restrict__ face, const float* __restrict__ alpha,
                    float* __restrict__ ctx)
{
    __shared__ float asum[SS];
    const int b = blockIdx.x;
    const int tid = threadIdx.x;

    float a = 0.f;
#pragma unroll
    for (int m = 0; m < MM; m++) a += alpha[b * (MM * SS) + m * SS + tid];
    asum[tid] = a;
    __syncthreads();

    const float* __restrict__ fb = face + (size_t)b * SS * 512;
    float c0 = 0.f, c1 = 0.f, c2 = 0.f, c3 = 0.f;
    for (int s = 0; s < SS; s += 4) {
        c0 = fmaf(asum[s + 0], fb[(size_t)(s + 0) * 512 + tid], c0);
        c1 = fmaf(asum[s + 1], fb[(size_t)(s + 1) * 512 + tid], c1);
        c2 = fmaf(asum[s + 2], fb[(size_t)(s + 2) * 512 + tid], c2);
        c3 = fmaf(asum[s + 3], fb[(size_t)(s + 3) * 512 + tid], c3);
    }
    ctx[b * 512 + tid] = (c0 + c1) + (c2 + c3);
}

// ---------------------------------------------------------------------------
// Launch. Inputs: 0 fc, 1 img, 2 label, 3 memory, 4 face, 5 face_mask,
// 6 W1, 7 b1, 8 w2.  Output: alpha [B, M*S] then context [B, DF].
// ---------------------------------------------------------------------------
extern "C" void kernel_launch(void* const* d_in, const int* in_sizes, int n_in,
                              void* d_out, int out_size)
{
    const float* fc     = (const float*)d_in[0];
    const float* img    = (const float*)d_in[1];
    const float* label  = (const float*)d_in[2];
    const float* memory = (const float*)d_in[3];
    const float* face   = (const float*)d_in[4];
    const float* fmask  = (const float*)d_in[5];
    const float* W1     = (const float*)d_in[6];
    const float* b1     = (const float*)d_in[7];
    const float* w2     = (const float*)d_in[8];

    float* out   = (float*)d_out;
    float* alpha = out;                      // [B, M*S]
    float* ctx   = out + BB * MM * SS;       // [B, DF]

    cudaFuncSetAttribute(gemm_pb_mma, cudaFuncAttributeMaxDynamicSharedMemorySize, DYN_SMEM);

    convert_w_kernel<<<(W4 + 255) / 256, 256>>>(W1);
    gemm_pb_mma<<<dim3(HH / GN, (BB * SS) / GM), 512, DYN_SMEM>>>(face, fc, img);
    pm_kernel<<<(BB * MM * HH) * 32 / 256, 256>>>(memory, label, W1, b1);
    e_kernel<<<dim3(SS / 8, BB), 256>>>(w2);
    softmax_kernel<<<BB, 1024>>>(fmask, alpha);
    context_kernel<<<BB, 512>>>(face, alpha, ctx);
}